// round 1
// baseline (speedup 1.0000x reference)
#include <cuda_runtime.h>

#define BATCH 2
#define SEQ 2048
#define NHEAD 16
#define HD 64
#define EMB 1024
#define QKV_ELEMS (BATCH * NHEAD * SEQ * HD)

// Scratch (no cudaMalloc allowed): Q/K/V in [b][h][n][d] layout, 16 MB each.
__device__ float g_q[QKV_ELEMS];
__device__ float g_k[QKV_ELEMS];
__device__ float g_v[QKV_ELEMS];

__device__ __forceinline__ float warp_rowmax16(float v) {
    v = fmaxf(v, __shfl_xor_sync(0xffffffffu, v, 8));
    v = fmaxf(v, __shfl_xor_sync(0xffffffffu, v, 4));
    v = fmaxf(v, __shfl_xor_sync(0xffffffffu, v, 2));
    v = fmaxf(v, __shfl_xor_sync(0xffffffffu, v, 1));
    return v;
}
__device__ __forceinline__ float warp_rowsum16(float v) {
    v += __shfl_xor_sync(0xffffffffu, v, 8);
    v += __shfl_xor_sync(0xffffffffu, v, 4);
    v += __shfl_xor_sync(0xffffffffu, v, 2);
    v += __shfl_xor_sync(0xffffffffu, v, 1);
    return v;
}

// ---------------------------------------------------------------------------
// QKV projection: proj[b,h,n,f] = x[b,n,:] @ Wkqv[h,:,f] + bkqv[h,f]
// f split (torch order): [0:64)=K, [64:128)=Q, [128:192)=V
// grid (3 colTiles, 64 rowTiles, 16 heads), 256 threads, 64x64 tile, 4x4 frag
// ---------------------------------------------------------------------------
__global__ __launch_bounds__(256) void qkv_kernel(const float* __restrict__ x,
                                                  const float* __restrict__ W,
                                                  const float* __restrict__ bias)
{
    __shared__ float As[64][16];   // x tile, [row][k]
    __shared__ float Bs[16][64];   // W tile, [k][col]

    const int h       = blockIdx.z;
    const int rowBase = blockIdx.y * 64;    // (b,n) flat row
    const int colTile = blockIdx.x;         // 0=K, 1=Q, 2=V

    const int tid = threadIdx.x;
    const int ty = tid >> 4, tx = tid & 15;
    const int r0 = ty * 4, c0 = tx * 4;

    const int la_row = tid >> 2;
    const int la_k   = (tid & 3) * 4;
    const int lb_k   = tid >> 4;
    const int lb_c   = (tid & 15) * 4;

    const float* Wh = W + (size_t)h * (EMB * 192) + colTile * 64;

    float acc[4][4] = {};

    for (int k0 = 0; k0 < EMB; k0 += 16) {
        float4 av = *(const float4*)(x + (size_t)(rowBase + la_row) * EMB + (k0 + la_k));
        float4 bv = *(const float4*)(Wh + (size_t)(k0 + lb_k) * 192 + lb_c);
        *(float4*)&As[la_row][la_k] = av;
        *(float4*)&Bs[lb_k][lb_c]   = bv;
        __syncthreads();
        #pragma unroll
        for (int kk = 0; kk < 16; kk += 4) {
            float4 a4[4];
            #pragma unroll
            for (int i = 0; i < 4; i++) a4[i] = *(const float4*)&As[r0 + i][kk];
            #pragma unroll
            for (int t = 0; t < 4; t++) {
                float4 b = *(const float4*)&Bs[kk + t][c0];
                #pragma unroll
                for (int i = 0; i < 4; i++) {
                    float a = (&a4[i].x)[t];
                    acc[i][0] += a * b.x;
                    acc[i][1] += a * b.y;
                    acc[i][2] += a * b.z;
                    acc[i][3] += a * b.w;
                }
            }
        }
        __syncthreads();
    }

    float4 bb = *(const float4*)(bias + h * 192 + colTile * 64 + c0);
    float* dst = (colTile == 0) ? g_k : ((colTile == 1) ? g_q : g_v);
    #pragma unroll
    for (int i = 0; i < 4; i++) {
        int gr = rowBase + r0 + i;
        int b  = gr >> 11;          // /SEQ
        int n  = gr & (SEQ - 1);
        float4 ov = make_float4(acc[i][0] + bb.x, acc[i][1] + bb.y,
                                acc[i][2] + bb.z, acc[i][3] + bb.w);
        *(float4*)(dst + (((size_t)(b * NHEAD + h)) * SEQ + n) * HD + c0) = ov;
    }
}

// ---------------------------------------------------------------------------
// Causal flash attention, fp32. BR=BC=64, one block per (q-tile, b*h).
// Smem: Qs (16KB) + KP (K^T / P union, 16KB) + Vs (16KB) = 48KB static.
// Thread grid 16x16, each thread owns 4x4 frags of S/P and O.
// ---------------------------------------------------------------------------
__global__ __launch_bounds__(256) void attn_kernel(float* __restrict__ out)
{
    __shared__ float Qs[64][HD];   // [q][d]
    __shared__ float KP[64][64];   // phase 1: K^T [d][k]; phase 2: P [q][k]
    __shared__ float Vs[64][HD];   // [k][d]

    const int qtile = (int)gridDim.x - 1 - (int)blockIdx.x;  // heavy tiles first
    const int bh    = blockIdx.y;
    const int tid   = threadIdx.x;
    const int ty = tid >> 4, tx = tid & 15;
    const int r0 = ty * 4, c0 = tx * 4;

    const float* Qp = g_q + (size_t)bh * SEQ * HD;
    const float* Kp = g_k + (size_t)bh * SEQ * HD;
    const float* Vp = g_v + (size_t)bh * SEQ * HD;

    const int lrow = tid >> 2;
    const int ld0  = (tid & 3) * 16;

    // Load Q tile (natural layout, coalesced)
    #pragma unroll
    for (int i = 0; i < 4; i++) {
        float4 v = *(const float4*)(Qp + (size_t)(qtile * 64 + lrow) * HD + ld0 + i * 4);
        *(float4*)&Qs[lrow][ld0 + i * 4] = v;
    }

    float o[4][4] = {};
    float m[4] = {-1e30f, -1e30f, -1e30f, -1e30f};
    float l[4] = {0.f, 0.f, 0.f, 0.f};

    for (int jt = 0; jt <= qtile; jt++) {
        __syncthreads();   // prev PV GEMM done reading KP/Vs (and Q load visible)
        // Load K tile transposed (KP[d][k]) and V tile natural
        #pragma unroll
        for (int i = 0; i < 4; i++) {
            float4 kv = *(const float4*)(Kp + (size_t)(jt * 64 + lrow) * HD + ld0 + i * 4);
            KP[ld0 + i * 4 + 0][lrow] = kv.x;
            KP[ld0 + i * 4 + 1][lrow] = kv.y;
            KP[ld0 + i * 4 + 2][lrow] = kv.z;
            KP[ld0 + i * 4 + 3][lrow] = kv.w;
            float4 vv = *(const float4*)(Vp + (size_t)(jt * 64 + lrow) * HD + ld0 + i * 4);
            *(float4*)&Vs[lrow][ld0 + i * 4] = vv;
        }
        __syncthreads();

        // S = Q @ K^T  (Q frags broadcast, K frags bank-spread)
        float s[4][4] = {};
        #pragma unroll
        for (int d = 0; d < HD; d += 4) {
            float4 q4[4];
            #pragma unroll
            for (int i = 0; i < 4; i++) q4[i] = *(const float4*)&Qs[r0 + i][d];
            #pragma unroll
            for (int t = 0; t < 4; t++) {
                float4 kb = *(const float4*)&KP[d + t][c0];
                #pragma unroll
                for (int i = 0; i < 4; i++) {
                    float qv = (&q4[i].x)[t];
                    s[i][0] += qv * kb.x;
                    s[i][1] += qv * kb.y;
                    s[i][2] += qv * kb.z;
                    s[i][3] += qv * kb.w;
                }
            }
        }

        // scale + causal mask (diagonal tile only: local indices suffice)
        const float scale = 0.125f;   // 1/sqrt(64)
        if (jt == qtile) {
            #pragma unroll
            for (int i = 0; i < 4; i++)
                #pragma unroll
                for (int j = 0; j < 4; j++)
                    s[i][j] = (c0 + j <= r0 + i) ? s[i][j] * scale : -1e30f;
        } else {
            #pragma unroll
            for (int i = 0; i < 4; i++)
                #pragma unroll
                for (int j = 0; j < 4; j++)
                    s[i][j] *= scale;
        }

        // online softmax (row stats reduced across the 16 tx-lanes)
        #pragma unroll
        for (int i = 0; i < 4; i++) {
            float mt = fmaxf(fmaxf(s[i][0], s[i][1]), fmaxf(s[i][2], s[i][3]));
            mt = warp_rowmax16(mt);
            float mn = fmaxf(m[i], mt);
            float alpha = __expf(m[i] - mn);
            m[i] = mn;
            float rs = 0.f;
            #pragma unroll
            for (int j = 0; j < 4; j++) { s[i][j] = __expf(s[i][j] - mn); rs += s[i][j]; }
            rs = warp_rowsum16(rs);
            l[i] = l[i] * alpha + rs;
            #pragma unroll
            for (int j = 0; j < 4; j++) o[i][j] *= alpha;
        }

        __syncthreads();   // everyone done reading K^T from KP
        #pragma unroll
        for (int i = 0; i < 4; i++)
            *(float4*)&KP[r0 + i][c0] = make_float4(s[i][0], s[i][1], s[i][2], s[i][3]);
        __syncthreads();

        // O += P @ V  (P frags broadcast, V frags bank-spread)
        #pragma unroll
        for (int k = 0; k < 64; k += 4) {
            float4 p4[4];
            #pragma unroll
            for (int i = 0; i < 4; i++) p4[i] = *(const float4*)&KP[r0 + i][k];
            #pragma unroll
            for (int t = 0; t < 4; t++) {
                float4 vb = *(const float4*)&Vs[k + t][c0];
                #pragma unroll
                for (int i = 0; i < 4; i++) {
                    float pv = (&p4[i].x)[t];
                    o[i][0] += pv * vb.x;
                    o[i][1] += pv * vb.y;
                    o[i][2] += pv * vb.z;
                    o[i][3] += pv * vb.w;
                }
            }
        }
    }

    // epilogue: O /= l, write out[b, n, h*64 + d]
    const int b = bh >> 4, h = bh & (NHEAD - 1);
    #pragma unroll
    for (int i = 0; i < 4; i++) {
        float inv = 1.0f / l[i];
        int n = qtile * 64 + r0 + i;
        float4 ov = make_float4(o[i][0] * inv, o[i][1] * inv,
                                o[i][2] * inv, o[i][3] * inv);
        *(float4*)(out + ((size_t)(b * SEQ + n)) * EMB + h * HD + c0) = ov;
    }
}

extern "C" void kernel_launch(void* const* d_in, const int* in_sizes, int n_in,
                              void* d_out, int out_size)
{
    const float* x    = (const float*)d_in[0];  // [2,2048,1024]
    const float* W    = (const float*)d_in[1];  // [16,1024,192]
    const float* bias = (const float*)d_in[2];  // [16,192]
    float* out = (float*)d_out;                 // [2,2048,1024]

    dim3 g1(3, 64, NHEAD);
    qkv_kernel<<<g1, 256>>>(x, W, bias);

    dim3 g2(SEQ / 64, BATCH * NHEAD);
    attn_kernel<<<g2, 256>>>(out);
}

// round 3
// speedup vs baseline: 1.6354x; 1.6354x over previous
#include <cuda_runtime.h>
#include <cstdint>

#define BATCH 2
#define SEQ 2048
#define NHEAD 16
#define HD 64
#define EMB 1024
#define ROWS (BATCH * SEQ)          // 4096
#define FDIM 192
#define NTOT (NHEAD * FDIM)         // 3072
#define QKV_ELEMS (BATCH * NHEAD * SEQ * HD)

// Scratch (no cudaMalloc allowed)
__device__ __align__(1024) float g_q[QKV_ELEMS];
__device__ __align__(1024) float g_k[QKV_ELEMS];
__device__ __align__(1024) float g_v[QKV_ELEMS];
__device__ __align__(1024) float g_x32[ROWS * EMB];     // tf32-rounded x
__device__ __align__(1024) float g_wt[NTOT * EMB];      // tf32-rounded W^T [h*192+f][1024]

__device__ __forceinline__ uint32_t smem_u32(const void* p) {
    uint32_t a;
    asm("{ .reg .u64 t; cvta.to.shared.u64 t, %1; cvt.u32.u64 %0, t; }" : "=r"(a) : "l"(p));
    return a;
}
__device__ __forceinline__ float tf32r(float x) {
    uint32_t u;
    asm("cvt.rna.tf32.f32 %0, %1;" : "=r"(u) : "f"(x));
    return __uint_as_float(u);
}
__device__ __forceinline__ void cp16(uint32_t saddr, const void* gaddr) {
    asm volatile("cp.async.ca.shared.global [%0], [%1], 16;" :: "r"(saddr), "l"(gaddr));
}
__device__ __forceinline__ void cp_commit() {
    asm volatile("cp.async.commit_group;" ::: "memory");
}
template <int N>
__device__ __forceinline__ void cp_wait() {
    asm volatile("cp.async.wait_group %0;" :: "n"(N) : "memory");
}
__device__ __forceinline__ void mma_tf32(float* c, const uint32_t* a, const uint32_t* b) {
    asm volatile(
        "mma.sync.aligned.m16n8k8.row.col.f32.tf32.tf32.f32 "
        "{%0,%1,%2,%3}, {%4,%5,%6,%7}, {%8,%9}, {%0,%1,%2,%3};"
        : "+f"(c[0]), "+f"(c[1]), "+f"(c[2]), "+f"(c[3])
        : "r"(a[0]), "r"(a[1]), "r"(a[2]), "r"(a[3]), "r"(b[0]), "r"(b[1]));
}

// ---------------------------------------------------------------------------
// Prep: round x to tf32; transpose+round W -> Wt[h*192+f][1024]
// ---------------------------------------------------------------------------
__global__ void round_x_kernel(const float4* __restrict__ x) {
    int i = blockIdx.x * blockDim.x + threadIdx.x;
    float4 v = x[i];
    ((float4*)g_x32)[i] = make_float4(tf32r(v.x), tf32r(v.y), tf32r(v.z), tf32r(v.w));
}

__global__ void wtrans_kernel(const float* __restrict__ W) {
    __shared__ float t[32][33];
    int h = blockIdx.z, d0 = blockIdx.x * 32, f0 = blockIdx.y * 32;
    int x = threadIdx.x, y = threadIdx.y;  // 32 x 8
    const float* Wh = W + (size_t)h * EMB * FDIM;
    #pragma unroll
    for (int j = 0; j < 32; j += 8)
        t[y + j][x] = tf32r(Wh[(size_t)(d0 + y + j) * FDIM + f0 + x]);
    __syncthreads();
    #pragma unroll
    for (int j = 0; j < 32; j += 8)
        g_wt[(size_t)(h * FDIM + f0 + y + j) * EMB + d0 + x] = t[x][y + j];
}

// ---------------------------------------------------------------------------
// QKV GEMM: C[4096, 3072] = x32 @ Wt^T via mma.sync tf32.
// CTA 256x128x32, 3-stage cp.async pipeline, 8 warps (4m x 2n), warp 64x64.
// ---------------------------------------------------------------------------
static constexpr int CTA_M = 256;
static constexpr int CTA_N = 128;
static constexpr int CTA_K = 32;
static constexpr int STAGES = 3;
static constexpr int LDA = CTA_K + 4;           // 36 floats, pad for conflict-free LDS
static constexpr int A_FLOATS = CTA_M * LDA;    // 9216
static constexpr int B_FLOATS = CTA_N * LDA;    // 4608
static constexpr int STAGE_FLOATS = A_FLOATS + B_FLOATS;  // 13824
static constexpr int SMEM_BYTES = STAGES * STAGE_FLOATS * 4;  // 165888
static constexpr int KITERS = EMB / CTA_K;      // 32

__global__ __launch_bounds__(256, 1) void qkv_mma_kernel(const float* __restrict__ bias)
{
    extern __shared__ float sm[];
    const int tid = threadIdx.x;
    const int wid = tid >> 5, lane = tid & 31;
    const int l4 = lane & 3, l8 = lane >> 2;
    const int rowBase = blockIdx.x * CTA_M;
    const int colBase = blockIdx.y * CTA_N;
    const int warp_m0 = (wid & 3) * 64;
    const int warp_n0 = (wid >> 2) * 64;

    const uint32_t smem_base = smem_u32(sm);
    const float* gA = g_x32 + (size_t)rowBase * EMB;
    const float* gB = g_wt + (size_t)colBase * EMB;

    // Per-thread load assignments (12 x 16B chunks per stage)
    // A: 2048 chunks (256 rows x 8), B: 1024 chunks (128 rows x 8)
    auto load_stage = [&](int s, int k0) {
        uint32_t As = smem_base + (s * STAGE_FLOATS) * 4;
        uint32_t Bs = As + A_FLOATS * 4;
        #pragma unroll
        for (int q = 0; q < 8; q++) {
            int c = tid + q * 256;
            int row = c >> 3, kc = (c & 7) * 4;
            cp16(As + (row * LDA + kc) * 4, gA + (size_t)row * EMB + k0 + kc);
        }
        #pragma unroll
        for (int q = 0; q < 4; q++) {
            int c = tid + q * 256;
            int row = c >> 3, kc = (c & 7) * 4;
            cp16(Bs + (row * LDA + kc) * 4, gB + (size_t)row * EMB + k0 + kc);
        }
    };

    float acc[4][8][4];
    #pragma unroll
    for (int i = 0; i < 4; i++)
        #pragma unroll
        for (int j = 0; j < 8; j++)
            #pragma unroll
            for (int r = 0; r < 4; r++) acc[i][j][r] = 0.f;

    // Prologue: stages 0,1
    load_stage(0, 0);
    cp_commit();
    load_stage(1, CTA_K);
    cp_commit();

    for (int it = 0; it < KITERS; it++) {
        if (it + 2 < KITERS) load_stage((it + 2) % STAGES, (it + 2) * CTA_K);
        cp_commit();
        cp_wait<2>();
        __syncthreads();

        const float* As = sm + (it % STAGES) * STAGE_FLOATS;
        const float* Bs = As + A_FLOATS;

        #pragma unroll
        for (int kk = 0; kk < CTA_K; kk += 8) {
            uint32_t a[4][4], b[8][2];
            #pragma unroll
            for (int mi = 0; mi < 4; mi++) {
                const float* p = As + (warp_m0 + mi * 16 + l8) * LDA + kk + l4;
                a[mi][0] = __float_as_uint(p[0]);
                a[mi][1] = __float_as_uint(p[8 * LDA]);
                a[mi][2] = __float_as_uint(p[4]);
                a[mi][3] = __float_as_uint(p[8 * LDA + 4]);
            }
            #pragma unroll
            for (int nj = 0; nj < 8; nj++) {
                const float* p = Bs + (warp_n0 + nj * 8 + l8) * LDA + kk + l4;
                b[nj][0] = __float_as_uint(p[0]);
                b[nj][1] = __float_as_uint(p[4]);
            }
            #pragma unroll
            for (int mi = 0; mi < 4; mi++)
                #pragma unroll
                for (int nj = 0; nj < 8; nj++)
                    mma_tf32(acc[mi][nj], a[mi], b[nj]);
        }
        __syncthreads();
    }

    // Epilogue: add bias, scatter into g_k / g_q / g_v  ([b][h][n][d] layout)
    #pragma unroll
    for (int mi = 0; mi < 4; mi++) {
        #pragma unroll
        for (int nj = 0; nj < 8; nj++) {
            int row0 = rowBase + warp_m0 + mi * 16 + l8;
            int n = colBase + warp_n0 + nj * 8 + 2 * l4;
            int h = n / FDIM, f = n - h * FDIM;
            float* dstbuf = (f < 64) ? g_k : ((f < 128) ? g_q : g_v);
            int fd = f & 63;
            float2 bv = *(const float2*)(bias + h * FDIM + f);
            #pragma unroll
            for (int half = 0; half < 2; half++) {
                int r = row0 + half * 8;
                int b = r >> 11, ns = r & (SEQ - 1);
                float2 ov = make_float2(acc[mi][nj][half * 2 + 0] + bv.x,
                                        acc[mi][nj][half * 2 + 1] + bv.y);
                *(float2*)(dstbuf + (((size_t)(b * NHEAD + h)) * SEQ + ns) * HD + fd) = ov;
            }
        }
    }
}

// ---------------------------------------------------------------------------
// Causal flash attention, fp32 (unchanged — known correct, ~670us)
// ---------------------------------------------------------------------------
__device__ __forceinline__ float warp_rowmax16(float v) {
    v = fmaxf(v, __shfl_xor_sync(0xffffffffu, v, 8));
    v = fmaxf(v, __shfl_xor_sync(0xffffffffu, v, 4));
    v = fmaxf(v, __shfl_xor_sync(0xffffffffu, v, 2));
    v = fmaxf(v, __shfl_xor_sync(0xffffffffu, v, 1));
    return v;
}
__device__ __forceinline__ float warp_rowsum16(float v) {
    v += __shfl_xor_sync(0xffffffffu, v, 8);
    v += __shfl_xor_sync(0xffffffffu, v, 4);
    v += __shfl_xor_sync(0xffffffffu, v, 2);
    v += __shfl_xor_sync(0xffffffffu, v, 1);
    return v;
}

__global__ __launch_bounds__(256) void attn_kernel(float* __restrict__ out)
{
    __shared__ float Qs[64][HD];
    __shared__ float KP[64][64];
    __shared__ float Vs[64][HD];

    const int qtile = (int)gridDim.x - 1 - (int)blockIdx.x;
    const int bh    = blockIdx.y;
    const int tid   = threadIdx.x;
    const int ty = tid >> 4, tx = tid & 15;
    const int r0 = ty * 4, c0 = tx * 4;

    const float* Qp = g_q + (size_t)bh * SEQ * HD;
    const float* Kp = g_k + (size_t)bh * SEQ * HD;
    const float* Vp = g_v + (size_t)bh * SEQ * HD;

    const int lrow = tid >> 2;
    const int ld0  = (tid & 3) * 16;

    #pragma unroll
    for (int i = 0; i < 4; i++) {
        float4 v = *(const float4*)(Qp + (size_t)(qtile * 64 + lrow) * HD + ld0 + i * 4);
        *(float4*)&Qs[lrow][ld0 + i * 4] = v;
    }

    float o[4][4] = {};
    float m[4] = {-1e30f, -1e30f, -1e30f, -1e30f};
    float l[4] = {0.f, 0.f, 0.f, 0.f};

    for (int jt = 0; jt <= qtile; jt++) {
        __syncthreads();
        #pragma unroll
        for (int i = 0; i < 4; i++) {
            float4 kv = *(const float4*)(Kp + (size_t)(jt * 64 + lrow) * HD + ld0 + i * 4);
            KP[ld0 + i * 4 + 0][lrow] = kv.x;
            KP[ld0 + i * 4 + 1][lrow] = kv.y;
            KP[ld0 + i * 4 + 2][lrow] = kv.z;
            KP[ld0 + i * 4 + 3][lrow] = kv.w;
            float4 vv = *(const float4*)(Vp + (size_t)(jt * 64 + lrow) * HD + ld0 + i * 4);
            *(float4*)&Vs[lrow][ld0 + i * 4] = vv;
        }
        __syncthreads();

        float s[4][4] = {};
        #pragma unroll
        for (int d = 0; d < HD; d += 4) {
            float4 q4[4];
            #pragma unroll
            for (int i = 0; i < 4; i++) q4[i] = *(const float4*)&Qs[r0 + i][d];
            #pragma unroll
            for (int t = 0; t < 4; t++) {
                float4 kb = *(const float4*)&KP[d + t][c0];
                #pragma unroll
                for (int i = 0; i < 4; i++) {
                    float qv = (&q4[i].x)[t];
                    s[i][0] += qv * kb.x;
                    s[i][1] += qv * kb.y;
                    s[i][2] += qv * kb.z;
                    s[i][3] += qv * kb.w;
                }
            }
        }

        const float scale = 0.125f;
        if (jt == qtile) {
            #pragma unroll
            for (int i = 0; i < 4; i++)
                #pragma unroll
                for (int j = 0; j < 4; j++)
                    s[i][j] = (c0 + j <= r0 + i) ? s[i][j] * scale : -1e30f;
        } else {
            #pragma unroll
            for (int i = 0; i < 4; i++)
                #pragma unroll
                for (int j = 0; j < 4; j++)
                    s[i][j] *= scale;
        }

        #pragma unroll
        for (int i = 0; i < 4; i++) {
            float mt = fmaxf(fmaxf(s[i][0], s[i][1]), fmaxf(s[i][2], s[i][3]));
            mt = warp_rowmax16(mt);
            float mn = fmaxf(m[i], mt);
            float alpha = __expf(m[i] - mn);
            m[i] = mn;
            float rs = 0.f;
            #pragma unroll
            for (int j = 0; j < 4; j++) { s[i][j] = __expf(s[i][j] - mn); rs += s[i][j]; }
            rs = warp_rowsum16(rs);
            l[i] = l[i] * alpha + rs;
            #pragma unroll
            for (int j = 0; j < 4; j++) o[i][j] *= alpha;
        }

        __syncthreads();
        #pragma unroll
        for (int i = 0; i < 4; i++)
            *(float4*)&KP[r0 + i][c0] = make_float4(s[i][0], s[i][1], s[i][2], s[i][3]);
        __syncthreads();

        #pragma unroll
        for (int k = 0; k < 64; k += 4) {
            float4 p4[4];
            #pragma unroll
            for (int i = 0; i < 4; i++) p4[i] = *(const float4*)&KP[r0 + i][k];
            #pragma unroll
            for (int t = 0; t < 4; t++) {
                float4 vb = *(const float4*)&Vs[k + t][c0];
                #pragma unroll
                for (int i = 0; i < 4; i++) {
                    float pv = (&p4[i].x)[t];
                    o[i][0] += pv * vb.x;
                    o[i][1] += pv * vb.y;
                    o[i][2] += pv * vb.z;
                    o[i][3] += pv * vb.w;
                }
            }
        }
    }

    const int b = bh >> 4, h = bh & (NHEAD - 1);
    #pragma unroll
    for (int i = 0; i < 4; i++) {
        float inv = 1.0f / l[i];
        int n = qtile * 64 + r0 + i;
        float4 ov = make_float4(o[i][0] * inv, o[i][1] * inv,
                                o[i][2] * inv, o[i][3] * inv);
        *(float4*)(out + ((size_t)(b * SEQ + n)) * EMB + h * HD + c0) = ov;
    }
}

// ---------------------------------------------------------------------------
// Host launcher
// ---------------------------------------------------------------------------
extern "C" void kernel_launch(void* const* d_in, const int* in_sizes, int n_in,
                              void* d_out, int out_size)
{
    const float* x    = (const float*)d_in[0];  // [2,2048,1024]
    const float* W    = (const float*)d_in[1];  // [16,1024,192]
    const float* bias = (const float*)d_in[2];  // [16,192]
    float* out = (float*)d_out;                 // [2,2048,1024]

    round_x_kernel<<<(ROWS * EMB / 4) / 256, 256>>>((const float4*)x);
    wtrans_kernel<<<dim3(EMB / 32, FDIM / 32, NHEAD), dim3(32, 8)>>>(W);

    static bool smem_set = false;
    if (!smem_set) {
        cudaFuncSetAttribute(qkv_mma_kernel, cudaFuncAttributeMaxDynamicSharedMemorySize, SMEM_BYTES);
        smem_set = true;
    }
    qkv_mma_kernel<<<dim3(ROWS / CTA_M, NTOT / CTA_N), 256, SMEM_BYTES>>>(bias);

    attn_kernel<<<dim3(SEQ / 64, BATCH * NHEAD), 256>>>(out);
}

// round 4
// speedup vs baseline: 3.1561x; 1.9298x over previous
#include <cuda_runtime.h>
#include <cstdint>

#define BATCH 2
#define SEQ 2048
#define NHEAD 16
#define HD 64
#define EMB 1024
#define ROWS (BATCH * SEQ)          // 4096
#define FDIM 192
#define NTOT (NHEAD * FDIM)         // 3072
#define QKV_ELEMS (BATCH * NHEAD * SEQ * HD)

// Scratch (no cudaMalloc allowed)
__device__ __align__(1024) float g_q[QKV_ELEMS];   // tf32-rounded, pre-scaled by 0.125
__device__ __align__(1024) float g_k[QKV_ELEMS];   // tf32-rounded
__device__ __align__(1024) float g_v[QKV_ELEMS];   // tf32-rounded
__device__ __align__(1024) float g_x32[ROWS * EMB];
__device__ __align__(1024) float g_wt[NTOT * EMB];

__device__ __forceinline__ uint32_t smem_u32(const void* p) {
    uint32_t a;
    asm("{ .reg .u64 t; cvta.to.shared.u64 t, %1; cvt.u32.u64 %0, t; }" : "=r"(a) : "l"(p));
    return a;
}
__device__ __forceinline__ float tf32r(float x) {
    uint32_t u;
    asm("cvt.rna.tf32.f32 %0, %1;" : "=r"(u) : "f"(x));
    return __uint_as_float(u);
}
__device__ __forceinline__ void cp16(uint32_t saddr, const void* gaddr) {
    asm volatile("cp.async.ca.shared.global [%0], [%1], 16;" :: "r"(saddr), "l"(gaddr));
}
__device__ __forceinline__ void cp_commit() {
    asm volatile("cp.async.commit_group;" ::: "memory");
}
template <int N>
__device__ __forceinline__ void cp_wait() {
    asm volatile("cp.async.wait_group %0;" :: "n"(N) : "memory");
}
__device__ __forceinline__ void mma_tf32(float* c, const uint32_t* a, const uint32_t* b) {
    asm volatile(
        "mma.sync.aligned.m16n8k8.row.col.f32.tf32.tf32.f32 "
        "{%0,%1,%2,%3}, {%4,%5,%6,%7}, {%8,%9}, {%0,%1,%2,%3};"
        : "+f"(c[0]), "+f"(c[1]), "+f"(c[2]), "+f"(c[3])
        : "r"(a[0]), "r"(a[1]), "r"(a[2]), "r"(a[3]), "r"(b[0]), "r"(b[1]));
}

// ---------------------------------------------------------------------------
// Prep: round x to tf32; transpose+round W -> Wt[h*192+f][1024]
// ---------------------------------------------------------------------------
__global__ void round_x_kernel(const float4* __restrict__ x) {
    int i = blockIdx.x * blockDim.x + threadIdx.x;
    float4 v = x[i];
    ((float4*)g_x32)[i] = make_float4(tf32r(v.x), tf32r(v.y), tf32r(v.z), tf32r(v.w));
}

__global__ void wtrans_kernel(const float* __restrict__ W) {
    __shared__ float t[32][33];
    int h = blockIdx.z, d0 = blockIdx.x * 32, f0 = blockIdx.y * 32;
    int x = threadIdx.x, y = threadIdx.y;  // 32 x 8
    const float* Wh = W + (size_t)h * EMB * FDIM;
    #pragma unroll
    for (int j = 0; j < 32; j += 8)
        t[y + j][x] = tf32r(Wh[(size_t)(d0 + y + j) * FDIM + f0 + x]);
    __syncthreads();
    #pragma unroll
    for (int j = 0; j < 32; j += 8)
        g_wt[(size_t)(h * FDIM + f0 + y + j) * EMB + d0 + x] = t[x][y + j];
}

// ---------------------------------------------------------------------------
// QKV GEMM: C[4096, 3072] = x32 @ Wt^T via mma.sync tf32.
// CTA 256x128x32, 3-stage cp.async pipeline, 8 warps (4m x 2n), warp 64x64.
// ---------------------------------------------------------------------------
static constexpr int CTA_M = 256;
static constexpr int CTA_N = 128;
static constexpr int CTA_K = 32;
static constexpr int GSTAGES = 3;
static constexpr int LDA = CTA_K + 4;
static constexpr int A_FLOATS = CTA_M * LDA;
static constexpr int B_FLOATS = CTA_N * LDA;
static constexpr int STAGE_FLOATS = A_FLOATS + B_FLOATS;
static constexpr int SMEM_BYTES = GSTAGES * STAGE_FLOATS * 4;
static constexpr int KITERS = EMB / CTA_K;

__global__ __launch_bounds__(256, 1) void qkv_mma_kernel(const float* __restrict__ bias)
{
    extern __shared__ float sm[];
    const int tid = threadIdx.x;
    const int wid = tid >> 5, lane = tid & 31;
    const int l4 = lane & 3, l8 = lane >> 2;
    const int rowBase = blockIdx.x * CTA_M;
    const int colBase = blockIdx.y * CTA_N;
    const int warp_m0 = (wid & 3) * 64;
    const int warp_n0 = (wid >> 2) * 64;

    const uint32_t smem_base = smem_u32(sm);
    const float* gA = g_x32 + (size_t)rowBase * EMB;
    const float* gB = g_wt + (size_t)colBase * EMB;

    auto load_stage = [&](int s, int k0) {
        uint32_t As = smem_base + (s * STAGE_FLOATS) * 4;
        uint32_t Bs = As + A_FLOATS * 4;
        #pragma unroll
        for (int q = 0; q < 8; q++) {
            int c = tid + q * 256;
            int row = c >> 3, kc = (c & 7) * 4;
            cp16(As + (row * LDA + kc) * 4, gA + (size_t)row * EMB + k0 + kc);
        }
        #pragma unroll
        for (int q = 0; q < 4; q++) {
            int c = tid + q * 256;
            int row = c >> 3, kc = (c & 7) * 4;
            cp16(Bs + (row * LDA + kc) * 4, gB + (size_t)row * EMB + k0 + kc);
        }
    };

    float acc[4][8][4];
    #pragma unroll
    for (int i = 0; i < 4; i++)
        #pragma unroll
        for (int j = 0; j < 8; j++)
            #pragma unroll
            for (int r = 0; r < 4; r++) acc[i][j][r] = 0.f;

    load_stage(0, 0);
    cp_commit();
    load_stage(1, CTA_K);
    cp_commit();

    for (int it = 0; it < KITERS; it++) {
        if (it + 2 < KITERS) load_stage((it + 2) % GSTAGES, (it + 2) * CTA_K);
        cp_commit();
        cp_wait<2>();
        __syncthreads();

        const float* As = sm + (it % GSTAGES) * STAGE_FLOATS;
        const float* Bs = As + A_FLOATS;

        #pragma unroll
        for (int kk = 0; kk < CTA_K; kk += 8) {
            uint32_t a[4][4], b[8][2];
            #pragma unroll
            for (int mi = 0; mi < 4; mi++) {
                const float* p = As + (warp_m0 + mi * 16 + l8) * LDA + kk + l4;
                a[mi][0] = __float_as_uint(p[0]);
                a[mi][1] = __float_as_uint(p[8 * LDA]);
                a[mi][2] = __float_as_uint(p[4]);
                a[mi][3] = __float_as_uint(p[8 * LDA + 4]);
            }
            #pragma unroll
            for (int nj = 0; nj < 8; nj++) {
                const float* p = Bs + (warp_n0 + nj * 8 + l8) * LDA + kk + l4;
                b[nj][0] = __float_as_uint(p[0]);
                b[nj][1] = __float_as_uint(p[4]);
            }
            #pragma unroll
            for (int mi = 0; mi < 4; mi++)
                #pragma unroll
                for (int nj = 0; nj < 8; nj++)
                    mma_tf32(acc[mi][nj], a[mi], b[nj]);
        }
        __syncthreads();
    }

    // Epilogue: add bias, tf32-round (Q pre-scaled by 0.125), scatter to g_k/g_q/g_v
    #pragma unroll
    for (int mi = 0; mi < 4; mi++) {
        #pragma unroll
        for (int nj = 0; nj < 8; nj++) {
            int row0 = rowBase + warp_m0 + mi * 16 + l8;
            int n = colBase + warp_n0 + nj * 8 + 2 * l4;
            int h = n / FDIM, f = n - h * FDIM;
            float* dstbuf = (f < 64) ? g_k : ((f < 128) ? g_q : g_v);
            float sc = (f >= 64 && f < 128) ? 0.125f : 1.0f;
            int fd = f & 63;
            float2 bv = *(const float2*)(bias + h * FDIM + f);
            #pragma unroll
            for (int half = 0; half < 2; half++) {
                int r = row0 + half * 8;
                int b = r >> 11, ns = r & (SEQ - 1);
                float2 ov = make_float2(tf32r((acc[mi][nj][half * 2 + 0] + bv.x) * sc),
                                        tf32r((acc[mi][nj][half * 2 + 1] + bv.y) * sc));
                *(float2*)(dstbuf + (((size_t)(b * NHEAD + h)) * SEQ + ns) * HD + fd) = ov;
            }
        }
    }
}

// ---------------------------------------------------------------------------
// Causal flash attention via mma.sync tf32.
// CTA: 256 queries x one bh; 8 warps x 32 query rows. Keys: 64-wide cp.async
// double-buffered tiles, computed in 32-key sub-chunks. P via per-warp smem.
// ---------------------------------------------------------------------------
static constexpr int ALDQ = 72;   // Q/K/V smem row stride (72 mod 32 = 8 -> CF frags)
static constexpr int ALDP = 40;   // P smem row stride
static constexpr int OFF_Q  = 0;                       // 256*72 = 18432 floats
static constexpr int KV_FLOATS = 64 * ALDQ;            // 4608
static constexpr int OFF_KV = 18432;                   // K0 V0 K1 V1
static constexpr int OFF_P  = OFF_KV + 4 * KV_FLOATS;  // 36864
static constexpr int ATT_SMEM = (OFF_P + 8 * 32 * ALDP) * 4;  // 188416 B

__global__ __launch_bounds__(256, 1) void attn_mma_kernel(float* __restrict__ out)
{
    extern __shared__ float sm[];
    const int tid = threadIdx.x, wid = tid >> 5, lane = tid & 31;
    const int l4 = lane & 3, l8 = lane >> 2;
    const int qt = (int)gridDim.x - 1 - (int)blockIdx.x;  // heavy tiles first
    const int bh = blockIdx.y;
    const int m0 = wid * 32;
    const int qbase = qt * 256;

    const float* Qg = g_q + (size_t)bh * SEQ * HD + (size_t)qbase * HD;
    const float* Kg = g_k + (size_t)bh * SEQ * HD;
    const float* Vg = g_v + (size_t)bh * SEQ * HD;

    const uint32_t sbase = smem_u32(sm);

    // Q tile: 256 rows x 64 d (16 cp16 per thread), group 0
    #pragma unroll
    for (int q = 0; q < 16; q++) {
        int c = tid + q * 256;
        int row = c >> 4, ch = (c & 15) * 4;
        cp16(sbase + (OFF_Q + row * ALDQ + ch) * 4, Qg + (size_t)row * HD + ch);
    }

    auto load_kv = [&](int stage, int jt) {
        uint32_t kb = sbase + (OFF_KV + stage * 2 * KV_FLOATS) * 4;
        const float* kg = Kg + (size_t)jt * 64 * HD;
        const float* vg = Vg + (size_t)jt * 64 * HD;
        #pragma unroll
        for (int q = 0; q < 4; q++) {
            int c = tid + q * 256;
            int row = c >> 4, ch = (c & 15) * 4;
            cp16(kb + (row * ALDQ + ch) * 4, kg + (size_t)row * HD + ch);
            cp16(kb + (KV_FLOATS + row * ALDQ + ch) * 4, vg + (size_t)row * HD + ch);
        }
    };

    const int ntiles = 4 * qt + 4;
    load_kv(0, 0);
    cp_commit();

    float oacc[2][8][4];
    #pragma unroll
    for (int i = 0; i < 2; i++)
        #pragma unroll
        for (int j = 0; j < 8; j++)
            #pragma unroll
            for (int r = 0; r < 4; r++) oacc[i][j][r] = 0.f;
    float mrow[2][2] = {{-1e30f, -1e30f}, {-1e30f, -1e30f}};
    float lrow[2][2] = {{0.f, 0.f}, {0.f, 0.f}};

    const int wrow_max = qbase + m0 + 31;
    float* Ps = sm + OFF_P + wid * 32 * ALDP;

    for (int jt = 0; jt < ntiles; jt++) {
        if (jt + 1 < ntiles) load_kv((jt + 1) & 1, jt + 1);
        cp_commit();
        cp_wait<1>();
        __syncthreads();

        const float* Ks = sm + OFF_KV + (jt & 1) * 2 * KV_FLOATS;
        const float* Vs = Ks + KV_FLOATS;

        #pragma unroll
        for (int sub = 0; sub < 2; sub++) {
            const int kc0 = jt * 64 + sub * 32;
            if (kc0 > wrow_max) continue;   // fully masked for this warp

            // ---- S = Q @ K^T (scale folded into Q) ----
            float sacc[2][4][4];
            #pragma unroll
            for (int i = 0; i < 2; i++)
                #pragma unroll
                for (int j = 0; j < 4; j++)
                    #pragma unroll
                    for (int r = 0; r < 4; r++) sacc[i][j][r] = 0.f;

            #pragma unroll
            for (int ks = 0; ks < 8; ks++) {
                uint32_t a[2][4], b[4][2];
                #pragma unroll
                for (int mf = 0; mf < 2; mf++) {
                    const float* p = sm + OFF_Q + (m0 + mf * 16 + l8) * ALDQ + ks * 8 + l4;
                    a[mf][0] = __float_as_uint(p[0]);
                    a[mf][1] = __float_as_uint(p[8 * ALDQ]);
                    a[mf][2] = __float_as_uint(p[4]);
                    a[mf][3] = __float_as_uint(p[8 * ALDQ + 4]);
                }
                #pragma unroll
                for (int nf = 0; nf < 4; nf++) {
                    const float* p = Ks + (sub * 32 + nf * 8 + l8) * ALDQ + ks * 8 + l4;
                    b[nf][0] = __float_as_uint(p[0]);
                    b[nf][1] = __float_as_uint(p[4]);
                }
                #pragma unroll
                for (int mf = 0; mf < 2; mf++)
                    #pragma unroll
                    for (int nf = 0; nf < 4; nf++)
                        mma_tf32(sacc[mf][nf], a[mf], b[nf]);
            }

            // ---- causal mask (diagonal chunk only) ----
            if (kc0 + 31 > qbase + m0) {
                #pragma unroll
                for (int mf = 0; mf < 2; mf++)
                    #pragma unroll
                    for (int r = 0; r < 2; r++) {
                        int qrow = qbase + m0 + mf * 16 + r * 8 + l8;
                        #pragma unroll
                        for (int nf = 0; nf < 4; nf++) {
                            int key = kc0 + nf * 8 + 2 * l4;
                            if (key > qrow)     sacc[mf][nf][r * 2 + 0] = -1e30f;
                            if (key + 1 > qrow) sacc[mf][nf][r * 2 + 1] = -1e30f;
                        }
                    }
            }

            // ---- online softmax (rows warp-local; reduce over 4 lanes) ----
            #pragma unroll
            for (int mf = 0; mf < 2; mf++)
                #pragma unroll
                for (int r = 0; r < 2; r++) {
                    float mx = -1e30f;
                    #pragma unroll
                    for (int nf = 0; nf < 4; nf++)
                        mx = fmaxf(mx, fmaxf(sacc[mf][nf][r * 2], sacc[mf][nf][r * 2 + 1]));
                    mx = fmaxf(mx, __shfl_xor_sync(0xffffffffu, mx, 1));
                    mx = fmaxf(mx, __shfl_xor_sync(0xffffffffu, mx, 2));
                    float mn = fmaxf(mrow[mf][r], mx);
                    float alpha = __expf(mrow[mf][r] - mn);
                    mrow[mf][r] = mn;
                    float rs = 0.f;
                    #pragma unroll
                    for (int nf = 0; nf < 4; nf++) {
                        float e0 = __expf(sacc[mf][nf][r * 2] - mn);
                        float e1 = __expf(sacc[mf][nf][r * 2 + 1] - mn);
                        sacc[mf][nf][r * 2] = e0;
                        sacc[mf][nf][r * 2 + 1] = e1;
                        rs += e0 + e1;
                    }
                    rs += __shfl_xor_sync(0xffffffffu, rs, 1);
                    rs += __shfl_xor_sync(0xffffffffu, rs, 2);
                    lrow[mf][r] = lrow[mf][r] * alpha + rs;
                    #pragma unroll
                    for (int nf = 0; nf < 8; nf++) {
                        oacc[mf][nf][r * 2] *= alpha;
                        oacc[mf][nf][r * 2 + 1] *= alpha;
                    }
                }

            // ---- P -> smem (tf32-rounded) ----
            __syncwarp();   // prior PV reads of Ps done
            #pragma unroll
            for (int mf = 0; mf < 2; mf++)
                #pragma unroll
                for (int nf = 0; nf < 4; nf++)
                    #pragma unroll
                    for (int r = 0; r < 2; r++) {
                        float2 pv = make_float2(tf32r(sacc[mf][nf][r * 2]),
                                                tf32r(sacc[mf][nf][r * 2 + 1]));
                        *(float2*)&Ps[(mf * 16 + r * 8 + l8) * ALDP + nf * 8 + 2 * l4] = pv;
                    }
            __syncwarp();

            // ---- O += P @ V ----
            #pragma unroll
            for (int ks = 0; ks < 4; ks++) {
                uint32_t a[2][4], b[8][2];
                #pragma unroll
                for (int mf = 0; mf < 2; mf++) {
                    const float* p = Ps + (mf * 16 + l8) * ALDP + ks * 8 + l4;
                    a[mf][0] = __float_as_uint(p[0]);
                    a[mf][1] = __float_as_uint(p[8 * ALDP]);
                    a[mf][2] = __float_as_uint(p[4]);
                    a[mf][3] = __float_as_uint(p[8 * ALDP + 4]);
                }
                #pragma unroll
                for (int nf = 0; nf < 8; nf++) {
                    const float* p = Vs + (sub * 32 + ks * 8 + l4) * ALDQ + nf * 8 + l8;
                    b[nf][0] = __float_as_uint(p[0]);
                    b[nf][1] = __float_as_uint(p[4 * ALDQ]);
                }
                #pragma unroll
                for (int mf = 0; mf < 2; mf++)
                    #pragma unroll
                    for (int nf = 0; nf < 8; nf++)
                        mma_tf32(oacc[mf][nf], a[mf], b[nf]);
            }
        }
        __syncthreads();   // tile buffers consumed before next overwrite
    }

    // ---- epilogue: O /= l, write out[b, n, h*64+d] ----
    const int b = bh >> 4, h = bh & (NHEAD - 1);
    #pragma unroll
    for (int mf = 0; mf < 2; mf++)
        #pragma unroll
        for (int r = 0; r < 2; r++) {
            int qrow = qbase + m0 + mf * 16 + r * 8 + l8;
            float inv = 1.0f / lrow[mf][r];
            float* op = out + ((size_t)(b * SEQ + qrow)) * EMB + h * HD;
            #pragma unroll
            for (int nf = 0; nf < 8; nf++) {
                float2 ov = make_float2(oacc[mf][nf][r * 2] * inv,
                                        oacc[mf][nf][r * 2 + 1] * inv);
                *(float2*)(op + nf * 8 + 2 * l4) = ov;
            }
        }
}

// ---------------------------------------------------------------------------
// Host launcher
// ---------------------------------------------------------------------------
extern "C" void kernel_launch(void* const* d_in, const int* in_sizes, int n_in,
                              void* d_out, int out_size)
{
    const float* x    = (const float*)d_in[0];  // [2,2048,1024]
    const float* W    = (const float*)d_in[1];  // [16,1024,192]
    const float* bias = (const float*)d_in[2];  // [16,192]
    float* out = (float*)d_out;                 // [2,2048,1024]

    round_x_kernel<<<(ROWS * EMB / 4) / 256, 256>>>((const float4*)x);
    wtrans_kernel<<<dim3(EMB / 32, FDIM / 32, NHEAD), dim3(32, 8)>>>(W);

    static bool smem_set = false;
    if (!smem_set) {
        cudaFuncSetAttribute(qkv_mma_kernel, cudaFuncAttributeMaxDynamicSharedMemorySize, SMEM_BYTES);
        cudaFuncSetAttribute(attn_mma_kernel, cudaFuncAttributeMaxDynamicSharedMemorySize, ATT_SMEM);
        smem_set = true;
    }
    qkv_mma_kernel<<<dim3(ROWS / CTA_M, NTOT / CTA_N), 256, SMEM_BYTES>>>(bias);

    attn_mma_kernel<<<dim3(SEQ / 256, BATCH * NHEAD), 256, ATT_SMEM>>>(out);
}

// round 5
// speedup vs baseline: 6.1020x; 1.9334x over previous
#include <cuda_runtime.h>
#include <cuda_fp16.h>
#include <cstdint>

#define BATCH 2
#define SEQ 2048
#define NHEAD 16
#define HD 64
#define EMB 1024
#define ROWS (BATCH * SEQ)          // 4096
#define FDIM 192
#define NTOT (NHEAD * FDIM)         // 3072
#define QKV_ELEMS (BATCH * NHEAD * SEQ * HD)

// Scratch (no cudaMalloc allowed) — all fp16
__device__ __align__(1024) __half g_q[QKV_ELEMS];   // pre-scaled by 0.125
__device__ __align__(1024) __half g_k[QKV_ELEMS];
__device__ __align__(1024) __half g_v[QKV_ELEMS];
__device__ __align__(1024) __half g_xh[ROWS * EMB];
__device__ __align__(1024) __half g_wth[NTOT * EMB];   // W^T [h*192+f][1024]

// ---------------------------------------------------------------------------
// PTX helpers
// ---------------------------------------------------------------------------
__device__ __forceinline__ uint32_t smem_u32(const void* p) {
    uint32_t a;
    asm("{ .reg .u64 t; cvta.to.shared.u64 t, %1; cvt.u32.u64 %0, t; }" : "=r"(a) : "l"(p));
    return a;
}
__device__ __forceinline__ void cp16(uint32_t saddr, const void* gaddr) {
    asm volatile("cp.async.ca.shared.global [%0], [%1], 16;" :: "r"(saddr), "l"(gaddr));
}
__device__ __forceinline__ void cp_commit() {
    asm volatile("cp.async.commit_group;" ::: "memory");
}
template <int N>
__device__ __forceinline__ void cp_wait() {
    asm volatile("cp.async.wait_group %0;" :: "n"(N) : "memory");
}
__device__ __forceinline__ void ldmx4(uint32_t* r, uint32_t addr) {
    asm volatile("ldmatrix.sync.aligned.m8n8.x4.shared.b16 {%0,%1,%2,%3}, [%4];"
                 : "=r"(r[0]), "=r"(r[1]), "=r"(r[2]), "=r"(r[3]) : "r"(addr));
}
__device__ __forceinline__ void ldmx4t(uint32_t* r, uint32_t addr) {
    asm volatile("ldmatrix.sync.aligned.m8n8.x4.trans.shared.b16 {%0,%1,%2,%3}, [%4];"
                 : "=r"(r[0]), "=r"(r[1]), "=r"(r[2]), "=r"(r[3]) : "r"(addr));
}
__device__ __forceinline__ void mma_f16(float* c, const uint32_t* a, uint32_t b0, uint32_t b1) {
    asm volatile(
        "mma.sync.aligned.m16n8k16.row.col.f32.f16.f16.f32 "
        "{%0,%1,%2,%3}, {%4,%5,%6,%7}, {%8,%9}, {%0,%1,%2,%3};"
        : "+f"(c[0]), "+f"(c[1]), "+f"(c[2]), "+f"(c[3])
        : "r"(a[0]), "r"(a[1]), "r"(a[2]), "r"(a[3]), "r"(b0), "r"(b1));
}

// ---------------------------------------------------------------------------
// Prep: round x to fp16; transpose+round W -> Wt[h*192+f][1024] fp16
// ---------------------------------------------------------------------------
__global__ void round_x_kernel(const float4* __restrict__ x) {
    int i = blockIdx.x * blockDim.x + threadIdx.x;
    float4 v = x[i];
    ((__half2*)g_xh)[2 * i + 0] = __floats2half2_rn(v.x, v.y);
    ((__half2*)g_xh)[2 * i + 1] = __floats2half2_rn(v.z, v.w);
}

__global__ void wtrans_kernel(const float* __restrict__ W) {
    __shared__ float t[32][33];
    int h = blockIdx.z, d0 = blockIdx.x * 32, f0 = blockIdx.y * 32;
    int x = threadIdx.x, y = threadIdx.y;  // 32 x 8
    const float* Wh = W + (size_t)h * EMB * FDIM;
    #pragma unroll
    for (int j = 0; j < 32; j += 8)
        t[y + j][x] = Wh[(size_t)(d0 + y + j) * FDIM + f0 + x];
    __syncthreads();
    #pragma unroll
    for (int j = 0; j < 32; j += 8)
        g_wth[(size_t)(h * FDIM + f0 + y + j) * EMB + d0 + x] = __float2half(t[x][y + j]);
}

// ---------------------------------------------------------------------------
// QKV GEMM fp16: C[4096, 3072] = xh @ Wt^T via mma.m16n8k16 + ldmatrix.
// CTA 256x128x32(h), 3-stage cp.async, 8 warps (4m x 2n), warp 64x64.
// ---------------------------------------------------------------------------
static constexpr int CTA_M = 256;
static constexpr int CTA_N = 128;
static constexpr int CTA_K = 32;           // halves per stage
static constexpr int GST = 3;
static constexpr int LDAh = 40;            // halves; 80 B rows (5x16 -> CF ldmatrix)
static constexpr int A_H = CTA_M * LDAh;   // 10240
static constexpr int B_H = CTA_N * LDAh;   // 5120
static constexpr int STG_H = A_H + B_H;    // 15360
static constexpr int QKV_SMEM = GST * STG_H * 2;  // 92160 B
static constexpr int KIT = EMB / CTA_K;    // 32

__global__ __launch_bounds__(256, 1) void qkv_mma_kernel(const float* __restrict__ bias)
{
    extern __shared__ __half smh[];
    const int tid = threadIdx.x;
    const int wid = tid >> 5, lane = tid & 31;
    const int t4 = lane & 3, g = lane >> 2;
    const int rowBase = blockIdx.x * CTA_M;
    const int colBase = blockIdx.y * CTA_N;
    const int warp_m0 = (wid & 3) * 64;
    const int warp_n0 = (wid >> 2) * 64;

    const uint32_t sb = smem_u32(smh);
    const __half* gA = g_xh + (size_t)rowBase * EMB;
    const __half* gB = g_wth + (size_t)colBase * EMB;

    auto load_stage = [&](int s, int k0) {
        uint32_t As = sb + (s * STG_H) * 2;
        uint32_t Bs = As + A_H * 2;
        #pragma unroll
        for (int q = 0; q < 4; q++) {          // A: 256 rows x 4 chunks(8h)
            int c = tid + q * 256;
            int row = c >> 2, ch = (c & 3) * 8;
            cp16(As + (row * LDAh + ch) * 2, gA + (size_t)row * EMB + k0 + ch);
        }
        #pragma unroll
        for (int q = 0; q < 2; q++) {          // B: 128 rows x 4 chunks
            int c = tid + q * 256;
            int row = c >> 2, ch = (c & 3) * 8;
            cp16(Bs + (row * LDAh + ch) * 2, gB + (size_t)row * EMB + k0 + ch);
        }
    };

    float acc[4][8][4];
    #pragma unroll
    for (int i = 0; i < 4; i++)
        #pragma unroll
        for (int j = 0; j < 8; j++)
            #pragma unroll
            for (int r = 0; r < 4; r++) acc[i][j][r] = 0.f;

    load_stage(0, 0);
    cp_commit();
    load_stage(1, CTA_K);
    cp_commit();

    const int lrow16 = lane & 15;
    const int lcol8 = (lane >> 4) * 8;

    for (int it = 0; it < KIT; it++) {
        if (it + 2 < KIT) load_stage((it + 2) % GST, (it + 2) * CTA_K);
        cp_commit();
        cp_wait<2>();
        __syncthreads();

        uint32_t As = sb + ((it % GST) * STG_H) * 2;
        uint32_t Bs = As + A_H * 2;

        #pragma unroll
        for (int kc = 0; kc < 2; kc++) {       // two k16 chunks
            uint32_t a[4][4];
            #pragma unroll
            for (int mi = 0; mi < 4; mi++)
                ldmx4(a[mi], As + ((warp_m0 + mi * 16 + lrow16) * LDAh + kc * 16 + lcol8) * 2);
            #pragma unroll
            for (int np = 0; np < 4; np++) {
                uint32_t bf[4];
                ldmx4(bf, Bs + ((warp_n0 + np * 16 + lrow16) * LDAh + kc * 16 + lcol8) * 2);
                #pragma unroll
                for (int mi = 0; mi < 4; mi++) {
                    mma_f16(acc[mi][2 * np + 0], a[mi], bf[0], bf[2]);
                    mma_f16(acc[mi][2 * np + 1], a[mi], bf[1], bf[3]);
                }
            }
        }
        __syncthreads();
    }

    // Epilogue: + bias, scale Q by 0.125, convert fp16, scatter to g_k/g_q/g_v
    #pragma unroll
    for (int mi = 0; mi < 4; mi++) {
        #pragma unroll
        for (int nj = 0; nj < 8; nj++) {
            int row0 = rowBase + warp_m0 + mi * 16 + g;
            int n = colBase + warp_n0 + nj * 8 + 2 * t4;
            int h = n / FDIM, f = n - h * FDIM;
            __half* dstbuf = (f < 64) ? g_k : ((f < 128) ? g_q : g_v);
            float sc = (f >= 64 && f < 128) ? 0.125f : 1.0f;
            int fd = f & 63;
            float2 bv = make_float2(bias[h * FDIM + f], bias[h * FDIM + f + 1]);
            #pragma unroll
            for (int half_ = 0; half_ < 2; half_++) {
                int r = row0 + half_ * 8;
                int b = r >> 11, ns = r & (SEQ - 1);
                __half2 ov = __floats2half2_rn((acc[mi][nj][half_ * 2 + 0] + bv.x) * sc,
                                               (acc[mi][nj][half_ * 2 + 1] + bv.y) * sc);
                *(__half2*)(dstbuf + (((size_t)(b * NHEAD + h)) * SEQ + ns) * HD + fd) = ov;
            }
        }
    }
}

// ---------------------------------------------------------------------------
// Causal flash attention fp16 (FA2-style). CTA: 128 queries x one bh,
// 8 warps x 16 rows. KV: 64-key double-buffered cp.async tiles.
// Q persistent in frags; P = S-acc register reuse (no smem roundtrip).
// ---------------------------------------------------------------------------
static constexpr int LDH = 72;                       // halves; 144 B rows (9x16 -> CF)
static constexpr int OFFQ = 0;                       // 128*72 = 9216 halves
static constexpr int KVT_H = 64 * LDH;               // 4608 halves per K or V tile
static constexpr int OFFKV = 128 * LDH;              // stages: [K V][K V]
static constexpr int ATT_SMEM = (OFFKV + 4 * KVT_H) * 2;  // 55296 B

__global__ __launch_bounds__(256, 2) void attn_fa_kernel(float* __restrict__ out)
{
    extern __shared__ __half sh[];
    const int tid = threadIdx.x, wid = tid >> 5, lane = tid & 31;
    const int t4 = lane & 3, g = lane >> 2;
    const int qt = (int)gridDim.x - 1 - (int)blockIdx.x;  // heavy tiles first
    const int bh = blockIdx.y;
    const int qbase = qt * 128;

    const __half* Qg = g_q + (size_t)bh * SEQ * HD + (size_t)qbase * HD;
    const __half* Kg = g_k + (size_t)bh * SEQ * HD;
    const __half* Vg = g_v + (size_t)bh * SEQ * HD;

    const uint32_t sb = smem_u32(sh);

    // Q: 128 rows x 8 chunks(8h) = 1024 cp16 -> 4/thread   (group 0)
    #pragma unroll
    for (int q = 0; q < 4; q++) {
        int c = tid + q * 256;
        int row = c >> 3, ch = (c & 7) * 8;
        cp16(sb + (OFFQ + row * LDH + ch) * 2, Qg + (size_t)row * HD + ch);
    }
    cp_commit();

    auto load_kv = [&](int st, int jt) {
        uint32_t kb = sb + (OFFKV + st * 2 * KVT_H) * 2;
        const __half* kg = Kg + (size_t)jt * 64 * HD;
        const __half* vg = Vg + (size_t)jt * 64 * HD;
        #pragma unroll
        for (int q = 0; q < 2; q++) {
            int c = tid + q * 256;
            int row = c >> 3, ch = (c & 7) * 8;
            cp16(kb + (row * LDH + ch) * 2, kg + (size_t)row * HD + ch);
            cp16(kb + (KVT_H + row * LDH + ch) * 2, vg + (size_t)row * HD + ch);
        }
    };

    load_kv(0, 0);
    cp_commit();
    cp_wait<1>();           // Q group done
    __syncthreads();

    // Persistent Q frags: 16 rows x 64 d = 4 k16 chunks
    const int lrow16 = lane & 15;
    const int lcol8 = (lane >> 4) * 8;
    uint32_t qf[4][4];
    #pragma unroll
    for (int kc = 0; kc < 4; kc++)
        ldmx4(qf[kc], sb + (OFFQ + (wid * 16 + lrow16) * LDH + kc * 16 + lcol8) * 2);

    float oacc[8][4];
    #pragma unroll
    for (int j = 0; j < 8; j++)
        #pragma unroll
        for (int r = 0; r < 4; r++) oacc[j][r] = 0.f;
    float mrow[2] = {-1e30f, -1e30f};
    float lrow[2] = {0.f, 0.f};

    const int wrmin = qbase + wid * 16;
    const int wrmax = wrmin + 15;
    const int ntiles = 2 * qt + 2;

    // V trans-ldmatrix lane addressing (quadrants)
    const int v_row = ((lane >> 4) << 3) + (lane & 7);   // key within 16
    const int v_col = ((lane >> 3) & 1) * 8;             // d within 16

    for (int jt = 0; jt < ntiles; jt++) {
        if (jt + 1 < ntiles) load_kv((jt + 1) & 1, jt + 1);
        cp_commit();
        cp_wait<1>();
        __syncthreads();

        const int kb0 = jt * 64;
        uint32_t Ks = sb + (OFFKV + (jt & 1) * 2 * KVT_H) * 2;
        uint32_t Vs = Ks + KVT_H * 2;

        if (kb0 <= wrmax) {
            // ---- S = Q @ K^T ----
            float sacc[8][4];
            #pragma unroll
            for (int j = 0; j < 8; j++)
                #pragma unroll
                for (int r = 0; r < 4; r++) sacc[j][r] = 0.f;

            #pragma unroll
            for (int kc = 0; kc < 4; kc++) {
                #pragma unroll
                for (int np = 0; np < 4; np++) {
                    uint32_t bf[4];
                    ldmx4(bf, Ks + ((np * 16 + lrow16) * LDH + kc * 16 + lcol8) * 2);
                    mma_f16(sacc[2 * np + 0], qf[kc], bf[0], bf[2]);
                    mma_f16(sacc[2 * np + 1], qf[kc], bf[1], bf[3]);
                }
            }

            // ---- causal mask (diagonal region only) ----
            if (kb0 + 63 > wrmin) {
                #pragma unroll
                for (int nf = 0; nf < 8; nf++) {
                    int key = kb0 + nf * 8 + 2 * t4;
                    #pragma unroll
                    for (int r = 0; r < 2; r++) {
                        int qrow = wrmin + r * 8 + g;
                        if (key > qrow)     sacc[nf][r * 2 + 0] = -1e30f;
                        if (key + 1 > qrow) sacc[nf][r * 2 + 1] = -1e30f;
                    }
                }
            }

            // ---- online softmax (rows: g and g+8; reduce over 4 t4-lanes) ----
            float alpha[2];
            #pragma unroll
            for (int r = 0; r < 2; r++) {
                float mx = -1e30f;
                #pragma unroll
                for (int nf = 0; nf < 8; nf++)
                    mx = fmaxf(mx, fmaxf(sacc[nf][r * 2], sacc[nf][r * 2 + 1]));
                mx = fmaxf(mx, __shfl_xor_sync(0xffffffffu, mx, 1));
                mx = fmaxf(mx, __shfl_xor_sync(0xffffffffu, mx, 2));
                float mn = fmaxf(mrow[r], mx);
                alpha[r] = __expf(mrow[r] - mn);
                mrow[r] = mn;
                float rs = 0.f;
                #pragma unroll
                for (int nf = 0; nf < 8; nf++) {
                    float e0 = __expf(sacc[nf][r * 2] - mn);
                    float e1 = __expf(sacc[nf][r * 2 + 1] - mn);
                    sacc[nf][r * 2] = e0;
                    sacc[nf][r * 2 + 1] = e1;
                    rs += e0 + e1;
                }
                rs += __shfl_xor_sync(0xffffffffu, rs, 1);
                rs += __shfl_xor_sync(0xffffffffu, rs, 2);
                lrow[r] = lrow[r] * alpha[r] + rs;
            }
            #pragma unroll
            for (int nf = 0; nf < 8; nf++) {
                oacc[nf][0] *= alpha[0]; oacc[nf][1] *= alpha[0];
                oacc[nf][2] *= alpha[1]; oacc[nf][3] *= alpha[1];
            }

            // ---- P: S-acc -> half2 A-frags (register reuse, no smem) ----
            uint32_t plo[8], phi[8];
            #pragma unroll
            for (int nf = 0; nf < 8; nf++) {
                __half2 h0 = __floats2half2_rn(sacc[nf][0], sacc[nf][1]);
                __half2 h1 = __floats2half2_rn(sacc[nf][2], sacc[nf][3]);
                plo[nf] = *(uint32_t*)&h0;
                phi[nf] = *(uint32_t*)&h1;
            }

            // ---- O += P @ V ----
            #pragma unroll
            for (int kc2 = 0; kc2 < 4; kc2++) {
                uint32_t a[4] = {plo[2 * kc2], phi[2 * kc2], plo[2 * kc2 + 1], phi[2 * kc2 + 1]};
                #pragma unroll
                for (int np = 0; np < 4; np++) {
                    uint32_t bf[4];
                    ldmx4t(bf, Vs + ((kc2 * 16 + v_row) * LDH + np * 16 + v_col) * 2);
                    mma_f16(oacc[2 * np + 0], a, bf[0], bf[2]);
                    mma_f16(oacc[2 * np + 1], a, bf[1], bf[3]);
                }
            }
        }
        __syncthreads();
    }

    // ---- epilogue: O /= l, write out[b, n, h*64+d] fp32 ----
    const int b = bh >> 4, h = bh & (NHEAD - 1);
    #pragma unroll
    for (int r = 0; r < 2; r++) {
        int qrow = qbase + wid * 16 + r * 8 + g;
        float inv = 1.0f / lrow[r];
        float* op = out + ((size_t)(b * SEQ + qrow)) * EMB + h * HD;
        #pragma unroll
        for (int nf = 0; nf < 8; nf++) {
            float2 ov = make_float2(oacc[nf][r * 2] * inv, oacc[nf][r * 2 + 1] * inv);
            *(float2*)(op + nf * 8 + 2 * t4) = ov;
        }
    }
}

// ---------------------------------------------------------------------------
// Host launcher
// ---------------------------------------------------------------------------
extern "C" void kernel_launch(void* const* d_in, const int* in_sizes, int n_in,
                              void* d_out, int out_size)
{
    const float* x    = (const float*)d_in[0];  // [2,2048,1024]
    const float* W    = (const float*)d_in[1];  // [16,1024,192]
    const float* bias = (const float*)d_in[2];  // [16,192]
    float* out = (float*)d_out;                 // [2,2048,1024]

    round_x_kernel<<<(ROWS * EMB / 4) / 256, 256>>>((const float4*)x);
    wtrans_kernel<<<dim3(EMB / 32, FDIM / 32, NHEAD), dim3(32, 8)>>>(W);

    static bool smem_set = false;
    if (!smem_set) {
        cudaFuncSetAttribute(qkv_mma_kernel, cudaFuncAttributeMaxDynamicSharedMemorySize, QKV_SMEM);
        cudaFuncSetAttribute(attn_fa_kernel, cudaFuncAttributeMaxDynamicSharedMemorySize, ATT_SMEM);
        smem_set = true;
    }
    qkv_mma_kernel<<<dim3(ROWS / CTA_M, NTOT / CTA_N), 256, QKV_SMEM>>>(bias);

    attn_fa_kernel<<<dim3(SEQ / 128, BATCH * NHEAD), 256, ATT_SMEM>>>(out);
}

// round 6
// speedup vs baseline: 6.2430x; 1.0231x over previous
#include <cuda_runtime.h>
#include <cuda_fp16.h>
#include <cstdint>

#define BATCH 2
#define SEQ 2048
#define NHEAD 16
#define HD 64
#define EMB 1024
#define ROWS (BATCH * SEQ)          // 4096
#define FDIM 192
#define NTOT (NHEAD * FDIM)         // 3072
#define QKV_ELEMS (BATCH * NHEAD * SEQ * HD)

// Scratch (no cudaMalloc allowed) — all fp16
__device__ __align__(1024) __half g_q[QKV_ELEMS];   // pre-scaled by 0.125*log2(e)
__device__ __align__(1024) __half g_k[QKV_ELEMS];
__device__ __align__(1024) __half g_v[QKV_ELEMS];
__device__ __align__(1024) __half g_xh[ROWS * EMB];
__device__ __align__(1024) __half g_wth[NTOT * EMB];   // W^T [h*192+f][1024]

// ---------------------------------------------------------------------------
// PTX helpers
// ---------------------------------------------------------------------------
__device__ __forceinline__ uint32_t smem_u32(const void* p) {
    uint32_t a;
    asm("{ .reg .u64 t; cvta.to.shared.u64 t, %1; cvt.u32.u64 %0, t; }" : "=r"(a) : "l"(p));
    return a;
}
__device__ __forceinline__ void cp16(uint32_t saddr, const void* gaddr) {
    asm volatile("cp.async.ca.shared.global [%0], [%1], 16;" :: "r"(saddr), "l"(gaddr));
}
__device__ __forceinline__ void cp_commit() {
    asm volatile("cp.async.commit_group;" ::: "memory");
}
template <int N>
__device__ __forceinline__ void cp_wait() {
    asm volatile("cp.async.wait_group %0;" :: "n"(N) : "memory");
}
__device__ __forceinline__ void ldmx4(uint32_t* r, uint32_t addr) {
    asm volatile("ldmatrix.sync.aligned.m8n8.x4.shared.b16 {%0,%1,%2,%3}, [%4];"
                 : "=r"(r[0]), "=r"(r[1]), "=r"(r[2]), "=r"(r[3]) : "r"(addr));
}
__device__ __forceinline__ void ldmx4t(uint32_t* r, uint32_t addr) {
    asm volatile("ldmatrix.sync.aligned.m8n8.x4.trans.shared.b16 {%0,%1,%2,%3}, [%4];"
                 : "=r"(r[0]), "=r"(r[1]), "=r"(r[2]), "=r"(r[3]) : "r"(addr));
}
__device__ __forceinline__ void mma_f16(float* c, const uint32_t* a, uint32_t b0, uint32_t b1) {
    asm volatile(
        "mma.sync.aligned.m16n8k16.row.col.f32.f16.f16.f32 "
        "{%0,%1,%2,%3}, {%4,%5,%6,%7}, {%8,%9}, {%0,%1,%2,%3};"
        : "+f"(c[0]), "+f"(c[1]), "+f"(c[2]), "+f"(c[3])
        : "r"(a[0]), "r"(a[1]), "r"(a[2]), "r"(a[3]), "r"(b0), "r"(b1));
}
__device__ __forceinline__ float ex2f(float x) {
    float y;
    asm("ex2.approx.f32 %0, %1;" : "=f"(y) : "f"(x));
    return y;
}

// ---------------------------------------------------------------------------
// Prep: round x to fp16; transpose+round W -> Wt[h*192+f][1024] fp16
// ---------------------------------------------------------------------------
__global__ void round_x_kernel(const float4* __restrict__ x) {
    int i = blockIdx.x * blockDim.x + threadIdx.x;
    float4 v = x[i];
    ((__half2*)g_xh)[2 * i + 0] = __floats2half2_rn(v.x, v.y);
    ((__half2*)g_xh)[2 * i + 1] = __floats2half2_rn(v.z, v.w);
}

__global__ void wtrans_kernel(const float* __restrict__ W) {
    __shared__ float t[32][33];
    int h = blockIdx.z, d0 = blockIdx.x * 32, f0 = blockIdx.y * 32;
    int x = threadIdx.x, y = threadIdx.y;  // 32 x 8
    const float* Wh = W + (size_t)h * EMB * FDIM;
    #pragma unroll
    for (int j = 0; j < 32; j += 8)
        t[y + j][x] = Wh[(size_t)(d0 + y + j) * FDIM + f0 + x];
    __syncthreads();
    #pragma unroll
    for (int j = 0; j < 32; j += 8)
        g_wth[(size_t)(h * FDIM + f0 + y + j) * EMB + d0 + x] = __float2half(t[x][y + j]);
}

// ---------------------------------------------------------------------------
// QKV GEMM fp16: C[4096, 3072] = xh @ Wt^T via mma.m16n8k16 + ldmatrix.
// CTA 128x128x64(h), 3-stage cp.async, 4 warps (2m x 2n), warp 64x64.
// 2 CTAs/SM (110KB smem) so sync phases interleave across CTAs.
// ---------------------------------------------------------------------------
static constexpr int CTA_M = 128;
static constexpr int CTA_N = 128;
static constexpr int CTA_K = 64;           // halves per stage
static constexpr int GST = 3;
static constexpr int LDAh = 72;            // halves; 144 B rows (9x16 -> CF ldmatrix)
static constexpr int A_H = CTA_M * LDAh;   // 9216
static constexpr int B_H = CTA_N * LDAh;   // 9216
static constexpr int STG_H = A_H + B_H;    // 18432
static constexpr int QKV_SMEM = GST * STG_H * 2;  // 110592 B
static constexpr int KIT = EMB / CTA_K;    // 16

__global__ __launch_bounds__(128, 2) void qkv_mma_kernel(const float* __restrict__ bias)
{
    extern __shared__ __half smh[];
    const int tid = threadIdx.x;
    const int wid = tid >> 5, lane = tid & 31;
    const int t4 = lane & 3, g = lane >> 2;
    const int rowBase = blockIdx.x * CTA_M;
    const int colBase = blockIdx.y * CTA_N;
    const int warp_m0 = (wid >> 1) * 64;
    const int warp_n0 = (wid & 1) * 64;

    const uint32_t sb = smem_u32(smh);
    const __half* gA = g_xh + (size_t)rowBase * EMB;
    const __half* gB = g_wth + (size_t)colBase * EMB;

    auto load_stage = [&](int s, int k0) {
        uint32_t As = sb + (s * STG_H) * 2;
        uint32_t Bs = As + A_H * 2;
        #pragma unroll
        for (int q = 0; q < 8; q++) {          // A: 128 rows x 8 chunks(8h)
            int c = tid + q * 128;
            int row = c >> 3, ch = (c & 7) * 8;
            cp16(As + (row * LDAh + ch) * 2, gA + (size_t)row * EMB + k0 + ch);
        }
        #pragma unroll
        for (int q = 0; q < 8; q++) {          // B: 128 rows x 8 chunks
            int c = tid + q * 128;
            int row = c >> 3, ch = (c & 7) * 8;
            cp16(Bs + (row * LDAh + ch) * 2, gB + (size_t)row * EMB + k0 + ch);
        }
    };

    float acc[4][8][4];
    #pragma unroll
    for (int i = 0; i < 4; i++)
        #pragma unroll
        for (int j = 0; j < 8; j++)
            #pragma unroll
            for (int r = 0; r < 4; r++) acc[i][j][r] = 0.f;

    load_stage(0, 0);
    cp_commit();
    load_stage(1, CTA_K);
    cp_commit();

    const int lrow16 = lane & 15;
    const int lcol8 = (lane >> 4) * 8;

    for (int it = 0; it < KIT; it++) {
        if (it + 2 < KIT) load_stage((it + 2) % GST, (it + 2) * CTA_K);
        cp_commit();
        cp_wait<2>();
        __syncthreads();

        uint32_t As = sb + ((it % GST) * STG_H) * 2;
        uint32_t Bs = As + A_H * 2;

        #pragma unroll
        for (int kc = 0; kc < 4; kc++) {       // four k16 chunks
            uint32_t a[4][4];
            #pragma unroll
            for (int mi = 0; mi < 4; mi++)
                ldmx4(a[mi], As + ((warp_m0 + mi * 16 + lrow16) * LDAh + kc * 16 + lcol8) * 2);
            #pragma unroll
            for (int np = 0; np < 4; np++) {
                uint32_t bf[4];
                ldmx4(bf, Bs + ((warp_n0 + np * 16 + lrow16) * LDAh + kc * 16 + lcol8) * 2);
                #pragma unroll
                for (int mi = 0; mi < 4; mi++) {
                    mma_f16(acc[mi][2 * np + 0], a[mi], bf[0], bf[2]);
                    mma_f16(acc[mi][2 * np + 1], a[mi], bf[1], bf[3]);
                }
            }
        }
        __syncthreads();
    }

    // Epilogue: + bias, scale Q by 0.125*log2e, convert fp16, scatter
    const float QSC = 0.1803368801f;   // 0.125 * log2(e)
    #pragma unroll
    for (int mi = 0; mi < 4; mi++) {
        #pragma unroll
        for (int nj = 0; nj < 8; nj++) {
            int row0 = rowBase + warp_m0 + mi * 16 + g;
            int n = colBase + warp_n0 + nj * 8 + 2 * t4;
            int h = n / FDIM, f = n - h * FDIM;
            __half* dstbuf = (f < 64) ? g_k : ((f < 128) ? g_q : g_v);
            float sc = (f >= 64 && f < 128) ? QSC : 1.0f;
            int fd = f & 63;
            float2 bv = make_float2(bias[h * FDIM + f], bias[h * FDIM + f + 1]);
            #pragma unroll
            for (int half_ = 0; half_ < 2; half_++) {
                int r = row0 + half_ * 8;
                int b = r >> 11, ns = r & (SEQ - 1);
                __half2 ov = __floats2half2_rn((acc[mi][nj][half_ * 2 + 0] + bv.x) * sc,
                                               (acc[mi][nj][half_ * 2 + 1] + bv.y) * sc);
                *(__half2*)(dstbuf + (((size_t)(b * NHEAD + h)) * SEQ + ns) * HD + fd) = ov;
            }
        }
    }
}

// ---------------------------------------------------------------------------
// Causal flash attention fp16 (FA2). CTA: 128 queries, 8 warps x 16 rows.
// KV: 64-key double-buffered cp.async tiles, computed as two pipelined 32-key
// halves: S-MMA(half1) is issued BEFORE softmax(half0) so tensor work overlaps
// the MUFU/shfl softmax phase. Softmax in log2 domain (scale folded into Q).
// ---------------------------------------------------------------------------
static constexpr int LDH = 72;                       // halves; 144 B rows
static constexpr int OFFQ = 0;                       // 128*72 halves
static constexpr int KVT_H = 64 * LDH;               // 4608 halves per K or V tile
static constexpr int OFFKV = 128 * LDH;
static constexpr int ATT_SMEM = (OFFKV + 4 * KVT_H) * 2;  // 55296 B

__global__ __launch_bounds__(256, 2) void attn_fa_kernel(float* __restrict__ out)
{
    extern __shared__ __half sh[];
    const int tid = threadIdx.x, wid = tid >> 5, lane = tid & 31;
    const int t4 = lane & 3, g = lane >> 2;
    const int qt = (int)gridDim.x - 1 - (int)blockIdx.x;  // heavy tiles first
    const int bh = blockIdx.y;
    const int qbase = qt * 128;

    const __half* Qg = g_q + (size_t)bh * SEQ * HD + (size_t)qbase * HD;
    const __half* Kg = g_k + (size_t)bh * SEQ * HD;
    const __half* Vg = g_v + (size_t)bh * SEQ * HD;

    const uint32_t sb = smem_u32(sh);

    #pragma unroll
    for (int q = 0; q < 4; q++) {
        int c = tid + q * 256;
        int row = c >> 3, ch = (c & 7) * 8;
        cp16(sb + (OFFQ + row * LDH + ch) * 2, Qg + (size_t)row * HD + ch);
    }
    cp_commit();

    auto load_kv = [&](int st, int jt) {
        uint32_t kb = sb + (OFFKV + st * 2 * KVT_H) * 2;
        const __half* kg = Kg + (size_t)jt * 64 * HD;
        const __half* vg = Vg + (size_t)jt * 64 * HD;
        #pragma unroll
        for (int q = 0; q < 2; q++) {
            int c = tid + q * 256;
            int row = c >> 3, ch = (c & 7) * 8;
            cp16(kb + (row * LDH + ch) * 2, kg + (size_t)row * HD + ch);
            cp16(kb + (KVT_H + row * LDH + ch) * 2, vg + (size_t)row * HD + ch);
        }
    };

    load_kv(0, 0);
    cp_commit();
    cp_wait<1>();
    __syncthreads();

    const int lrow16 = lane & 15;
    const int lcol8 = (lane >> 4) * 8;
    uint32_t qf[4][4];
    #pragma unroll
    for (int kc = 0; kc < 4; kc++)
        ldmx4(qf[kc], sb + (OFFQ + (wid * 16 + lrow16) * LDH + kc * 16 + lcol8) * 2);

    float oacc[8][4];
    #pragma unroll
    for (int j = 0; j < 8; j++)
        #pragma unroll
        for (int r = 0; r < 4; r++) oacc[j][r] = 0.f;
    float mrow[2] = {-1e30f, -1e30f};
    float lrow[2] = {0.f, 0.f};

    const int wrmin = qbase + wid * 16;
    const int wrmax = wrmin + 15;
    const int ntiles = 2 * qt + 2;

    const int v_row = ((lane >> 4) << 3) + (lane & 7);
    const int v_col = ((lane >> 3) & 1) * 8;

    // softmax + PV for one 32-key half. sacc: [4][4] covering keys h0..h0+31.
    auto half_tail = [&](float (*sacc)[4], int kh0, uint32_t Vs, int vbase) {
        // mask if the half overlaps the diagonal region
        if (kh0 + 31 > wrmin) {
            #pragma unroll
            for (int nf = 0; nf < 4; nf++) {
                int key = kh0 + nf * 8 + 2 * t4;
                #pragma unroll
                for (int r = 0; r < 2; r++) {
                    int qrow = wrmin + r * 8 + g;
                    if (key > qrow)     sacc[nf][r * 2 + 0] = -1e30f;
                    if (key + 1 > qrow) sacc[nf][r * 2 + 1] = -1e30f;
                }
            }
        }
        // online softmax (log2 domain)
        float alpha[2];
        #pragma unroll
        for (int r = 0; r < 2; r++) {
            float mx = fmaxf(fmaxf(fmaxf(sacc[0][r * 2], sacc[0][r * 2 + 1]),
                                   fmaxf(sacc[1][r * 2], sacc[1][r * 2 + 1])),
                             fmaxf(fmaxf(sacc[2][r * 2], sacc[2][r * 2 + 1]),
                                   fmaxf(sacc[3][r * 2], sacc[3][r * 2 + 1])));
            mx = fmaxf(mx, __shfl_xor_sync(0xffffffffu, mx, 1));
            mx = fmaxf(mx, __shfl_xor_sync(0xffffffffu, mx, 2));
            float mn = fmaxf(mrow[r], mx);
            alpha[r] = ex2f(mrow[r] - mn);
            mrow[r] = mn;
            float rs = 0.f;
            #pragma unroll
            for (int nf = 0; nf < 4; nf++) {
                float e0 = ex2f(sacc[nf][r * 2] - mn);
                float e1 = ex2f(sacc[nf][r * 2 + 1] - mn);
                sacc[nf][r * 2] = e0;
                sacc[nf][r * 2 + 1] = e1;
                rs += e0 + e1;
            }
            rs += __shfl_xor_sync(0xffffffffu, rs, 1);
            rs += __shfl_xor_sync(0xffffffffu, rs, 2);
            lrow[r] = lrow[r] * alpha[r] + rs;
        }
        #pragma unroll
        for (int nf = 0; nf < 8; nf++) {
            oacc[nf][0] *= alpha[0]; oacc[nf][1] *= alpha[0];
            oacc[nf][2] *= alpha[1]; oacc[nf][3] *= alpha[1];
        }
        // P frags (register reuse)
        uint32_t plo[4], phi[4];
        #pragma unroll
        for (int nf = 0; nf < 4; nf++) {
            __half2 h0 = __floats2half2_rn(sacc[nf][0], sacc[nf][1]);
            __half2 h1 = __floats2half2_rn(sacc[nf][2], sacc[nf][3]);
            plo[nf] = *(uint32_t*)&h0;
            phi[nf] = *(uint32_t*)&h1;
        }
        // O += P @ V   (keys vbase..vbase+31 of this KV tile)
        #pragma unroll
        for (int kc2 = 0; kc2 < 2; kc2++) {
            uint32_t a[4] = {plo[2 * kc2], phi[2 * kc2], plo[2 * kc2 + 1], phi[2 * kc2 + 1]};
            #pragma unroll
            for (int np = 0; np < 4; np++) {
                uint32_t bf[4];
                ldmx4t(bf, Vs + ((vbase + kc2 * 16 + v_row) * LDH + np * 16 + v_col) * 2);
                mma_f16(oacc[2 * np + 0], a, bf[0], bf[2]);
                mma_f16(oacc[2 * np + 1], a, bf[1], bf[3]);
            }
        }
    };

    for (int jt = 0; jt < ntiles; jt++) {
        if (jt + 1 < ntiles) load_kv((jt + 1) & 1, jt + 1);
        cp_commit();
        cp_wait<1>();
        __syncthreads();

        const int kb0 = jt * 64;
        uint32_t Ks = sb + (OFFKV + (jt & 1) * 2 * KVT_H) * 2;
        uint32_t Vs = Ks + KVT_H * 2;

        if (kb0 <= wrmax) {
            const bool have1 = (kb0 + 32) <= wrmax;

            // ---- S-MMA half0 (keys kb0..+31) ----
            float sa[4][4], sbv[4][4];
            #pragma unroll
            for (int j = 0; j < 4; j++)
                #pragma unroll
                for (int r = 0; r < 4; r++) { sa[j][r] = 0.f; sbv[j][r] = 0.f; }

            #pragma unroll
            for (int kc = 0; kc < 4; kc++) {
                #pragma unroll
                for (int np = 0; np < 2; np++) {
                    uint32_t bf[4];
                    ldmx4(bf, Ks + ((np * 16 + lrow16) * LDH + kc * 16 + lcol8) * 2);
                    mma_f16(sa[2 * np + 0], qf[kc], bf[0], bf[2]);
                    mma_f16(sa[2 * np + 1], qf[kc], bf[1], bf[3]);
                }
            }
            // ---- S-MMA half1 issued BEFORE softmax(half0): overlaps MUFU ----
            if (have1) {
                #pragma unroll
                for (int kc = 0; kc < 4; kc++) {
                    #pragma unroll
                    for (int np = 2; np < 4; np++) {
                        uint32_t bf[4];
                        ldmx4(bf, Ks + ((np * 16 + lrow16) * LDH + kc * 16 + lcol8) * 2);
                        mma_f16(sbv[2 * (np - 2) + 0], qf[kc], bf[0], bf[2]);
                        mma_f16(sbv[2 * (np - 2) + 1], qf[kc], bf[1], bf[3]);
                    }
                }
            }

            half_tail(sa, kb0, Vs, 0);
            if (have1) half_tail(sbv, kb0 + 32, Vs, 32);
        }
        __syncthreads();
    }

    // ---- epilogue ----
    const int b = bh >> 4, h = bh & (NHEAD - 1);
    #pragma unroll
    for (int r = 0; r < 2; r++) {
        int qrow = qbase + wid * 16 + r * 8 + g;
        float inv = 1.0f / lrow[r];
        float* op = out + ((size_t)(b * SEQ + qrow)) * EMB + h * HD;
        #pragma unroll
        for (int nf = 0; nf < 8; nf++) {
            float2 ov = make_float2(oacc[nf][r * 2] * inv, oacc[nf][r * 2 + 1] * inv);
            *(float2*)(op + nf * 8 + 2 * t4) = ov;
        }
    }
}

// ---------------------------------------------------------------------------
// Host launcher
// ---------------------------------------------------------------------------
extern "C" void kernel_launch(void* const* d_in, const int* in_sizes, int n_in,
                              void* d_out, int out_size)
{
    const float* x    = (const float*)d_in[0];  // [2,2048,1024]
    const float* W    = (const float*)d_in[1];  // [16,1024,192]
    const float* bias = (const float*)d_in[2];  // [16,192]
    float* out = (float*)d_out;                 // [2,2048,1024]

    round_x_kernel<<<(ROWS * EMB / 4) / 256, 256>>>((const float4*)x);
    wtrans_kernel<<<dim3(EMB / 32, FDIM / 32, NHEAD), dim3(32, 8)>>>(W);

    static bool smem_set = false;
    if (!smem_set) {
        cudaFuncSetAttribute(qkv_mma_kernel, cudaFuncAttributeMaxDynamicSharedMemorySize, QKV_SMEM);
        cudaFuncSetAttribute(attn_fa_kernel, cudaFuncAttributeMaxDynamicSharedMemorySize, ATT_SMEM);
        smem_set = true;
    }
    qkv_mma_kernel<<<dim3(ROWS / CTA_M, NTOT / CTA_N), 128, QKV_SMEM>>>(bias);

    attn_fa_kernel<<<dim3(SEQ / 128, BATCH * NHEAD), 256, ATT_SMEM>>>(out);
}

// round 7
// speedup vs baseline: 6.6653x; 1.0676x over previous
#include <cuda_runtime.h>
#include <cuda_fp16.h>
#include <cstdint>

#define BATCH 2
#define SEQ 2048
#define NHEAD 16
#define HD 64
#define EMB 1024
#define ROWS (BATCH * SEQ)          // 4096
#define FDIM 192
#define NTOT (NHEAD * FDIM)         // 3072
#define QKV_ELEMS (BATCH * NHEAD * SEQ * HD)

// Scratch (no cudaMalloc allowed) — all fp16
__device__ __align__(1024) __half g_q[QKV_ELEMS];   // pre-scaled by 0.125*log2(e)
__device__ __align__(1024) __half g_k[QKV_ELEMS];
__device__ __align__(1024) __half g_v[QKV_ELEMS];
__device__ __align__(1024) __half g_xh[ROWS * EMB];
__device__ __align__(1024) __half g_wth[NTOT * EMB];   // W^T [h*192+f][1024]

// ---------------------------------------------------------------------------
// PTX helpers
// ---------------------------------------------------------------------------
__device__ __forceinline__ uint32_t smem_u32(const void* p) {
    uint32_t a;
    asm("{ .reg .u64 t; cvta.to.shared.u64 t, %1; cvt.u32.u64 %0, t; }" : "=r"(a) : "l"(p));
    return a;
}
__device__ __forceinline__ void cp16(uint32_t saddr, const void* gaddr) {
    asm volatile("cp.async.ca.shared.global [%0], [%1], 16;" :: "r"(saddr), "l"(gaddr));
}
__device__ __forceinline__ void cp_commit() {
    asm volatile("cp.async.commit_group;" ::: "memory");
}
template <int N>
__device__ __forceinline__ void cp_wait() {
    asm volatile("cp.async.wait_group %0;" :: "n"(N) : "memory");
}
__device__ __forceinline__ void ldmx4(uint32_t* r, uint32_t addr) {
    asm volatile("ldmatrix.sync.aligned.m8n8.x4.shared.b16 {%0,%1,%2,%3}, [%4];"
                 : "=r"(r[0]), "=r"(r[1]), "=r"(r[2]), "=r"(r[3]) : "r"(addr));
}
__device__ __forceinline__ void ldmx4t(uint32_t* r, uint32_t addr) {
    asm volatile("ldmatrix.sync.aligned.m8n8.x4.trans.shared.b16 {%0,%1,%2,%3}, [%4];"
                 : "=r"(r[0]), "=r"(r[1]), "=r"(r[2]), "=r"(r[3]) : "r"(addr));
}
__device__ __forceinline__ void mma_f16(float* c, const uint32_t* a, uint32_t b0, uint32_t b1) {
    asm volatile(
        "mma.sync.aligned.m16n8k16.row.col.f32.f16.f16.f32 "
        "{%0,%1,%2,%3}, {%4,%5,%6,%7}, {%8,%9}, {%0,%1,%2,%3};"
        : "+f"(c[0]), "+f"(c[1]), "+f"(c[2]), "+f"(c[3])
        : "r"(a[0]), "r"(a[1]), "r"(a[2]), "r"(a[3]), "r"(b0), "r"(b1));
}
__device__ __forceinline__ float ex2f(float x) {
    float y;
    asm("ex2.approx.f32 %0, %1;" : "=f"(y) : "f"(x));
    return y;
}
__device__ __forceinline__ __half2 h2ex2(__half2 x) {
    __half2 y;
    asm("ex2.approx.f16x2 %0, %1;" : "=r"(*(uint32_t*)&y) : "r"(*(uint32_t*)&x));
    return y;
}

// ---------------------------------------------------------------------------
// Prep: round x to fp16; transpose+round W -> Wt[h*192+f][1024] fp16
// ---------------------------------------------------------------------------
__global__ void round_x_kernel(const float4* __restrict__ x) {
    int i = blockIdx.x * blockDim.x + threadIdx.x;
    float4 v = x[i];
    ((__half2*)g_xh)[2 * i + 0] = __floats2half2_rn(v.x, v.y);
    ((__half2*)g_xh)[2 * i + 1] = __floats2half2_rn(v.z, v.w);
}

__global__ void wtrans_kernel(const float* __restrict__ W) {
    __shared__ float t[32][33];
    int h = blockIdx.z, d0 = blockIdx.x * 32, f0 = blockIdx.y * 32;
    int x = threadIdx.x, y = threadIdx.y;  // 32 x 8
    const float* Wh = W + (size_t)h * EMB * FDIM;
    #pragma unroll
    for (int j = 0; j < 32; j += 8)
        t[y + j][x] = Wh[(size_t)(d0 + y + j) * FDIM + f0 + x];
    __syncthreads();
    #pragma unroll
    for (int j = 0; j < 32; j += 8)
        g_wth[(size_t)(h * FDIM + f0 + y + j) * EMB + d0 + x] = __float2half(t[x][y + j]);
}

// ---------------------------------------------------------------------------
// QKV GEMM fp16: C[4096, 3072] = xh @ Wt^T via mma.m16n8k16 + ldmatrix.
// CTA 128x128x64(h), 3-stage cp.async, 4 warps (2m x 2n), warp 64x64.
// ---------------------------------------------------------------------------
static constexpr int CTA_M = 128;
static constexpr int CTA_N = 128;
static constexpr int CTA_K = 64;           // halves per stage
static constexpr int GST = 3;
static constexpr int LDAh = 72;            // halves; 144 B rows (9x16 -> CF ldmatrix)
static constexpr int A_H = CTA_M * LDAh;   // 9216
static constexpr int B_H = CTA_N * LDAh;   // 9216
static constexpr int STG_H = A_H + B_H;    // 18432
static constexpr int QKV_SMEM = GST * STG_H * 2;  // 110592 B
static constexpr int KIT = EMB / CTA_K;    // 16

__global__ __launch_bounds__(128, 2) void qkv_mma_kernel(const float* __restrict__ bias)
{
    extern __shared__ __half smh[];
    const int tid = threadIdx.x;
    const int wid = tid >> 5, lane = tid & 31;
    const int t4 = lane & 3, g = lane >> 2;
    const int rowBase = blockIdx.x * CTA_M;
    const int colBase = blockIdx.y * CTA_N;
    const int warp_m0 = (wid >> 1) * 64;
    const int warp_n0 = (wid & 1) * 64;

    const uint32_t sb = smem_u32(smh);
    const __half* gA = g_xh + (size_t)rowBase * EMB;
    const __half* gB = g_wth + (size_t)colBase * EMB;

    auto load_stage = [&](int s, int k0) {
        uint32_t As = sb + (s * STG_H) * 2;
        uint32_t Bs = As + A_H * 2;
        #pragma unroll
        for (int q = 0; q < 8; q++) {
            int c = tid + q * 128;
            int row = c >> 3, ch = (c & 7) * 8;
            cp16(As + (row * LDAh + ch) * 2, gA + (size_t)row * EMB + k0 + ch);
        }
        #pragma unroll
        for (int q = 0; q < 8; q++) {
            int c = tid + q * 128;
            int row = c >> 3, ch = (c & 7) * 8;
            cp16(Bs + (row * LDAh + ch) * 2, gB + (size_t)row * EMB + k0 + ch);
        }
    };

    float acc[4][8][4];
    #pragma unroll
    for (int i = 0; i < 4; i++)
        #pragma unroll
        for (int j = 0; j < 8; j++)
            #pragma unroll
            for (int r = 0; r < 4; r++) acc[i][j][r] = 0.f;

    load_stage(0, 0);
    cp_commit();
    load_stage(1, CTA_K);
    cp_commit();

    const int lrow16 = lane & 15;
    const int lcol8 = (lane >> 4) * 8;

    for (int it = 0; it < KIT; it++) {
        if (it + 2 < KIT) load_stage((it + 2) % GST, (it + 2) * CTA_K);
        cp_commit();
        cp_wait<2>();
        __syncthreads();

        uint32_t As = sb + ((it % GST) * STG_H) * 2;
        uint32_t Bs = As + A_H * 2;

        #pragma unroll
        for (int kc = 0; kc < 4; kc++) {
            uint32_t a[4][4];
            #pragma unroll
            for (int mi = 0; mi < 4; mi++)
                ldmx4(a[mi], As + ((warp_m0 + mi * 16 + lrow16) * LDAh + kc * 16 + lcol8) * 2);
            #pragma unroll
            for (int np = 0; np < 4; np++) {
                uint32_t bf[4];
                ldmx4(bf, Bs + ((warp_n0 + np * 16 + lrow16) * LDAh + kc * 16 + lcol8) * 2);
                #pragma unroll
                for (int mi = 0; mi < 4; mi++) {
                    mma_f16(acc[mi][2 * np + 0], a[mi], bf[0], bf[2]);
                    mma_f16(acc[mi][2 * np + 1], a[mi], bf[1], bf[3]);
                }
            }
        }
        __syncthreads();
    }

    const float QSC = 0.1803368801f;   // 0.125 * log2(e)
    #pragma unroll
    for (int mi = 0; mi < 4; mi++) {
        #pragma unroll
        for (int nj = 0; nj < 8; nj++) {
            int row0 = rowBase + warp_m0 + mi * 16 + g;
            int n = colBase + warp_n0 + nj * 8 + 2 * t4;
            int h = n / FDIM, f = n - h * FDIM;
            __half* dstbuf = (f < 64) ? g_k : ((f < 128) ? g_q : g_v);
            float sc = (f >= 64 && f < 128) ? QSC : 1.0f;
            int fd = f & 63;
            float2 bv = make_float2(bias[h * FDIM + f], bias[h * FDIM + f + 1]);
            #pragma unroll
            for (int half_ = 0; half_ < 2; half_++) {
                int r = row0 + half_ * 8;
                int b = r >> 11, ns = r & (SEQ - 1);
                __half2 ov = __floats2half2_rn((acc[mi][nj][half_ * 2 + 0] + bv.x) * sc,
                                               (acc[mi][nj][half_ * 2 + 1] + bv.y) * sc);
                *(__half2*)(dstbuf + (((size_t)(b * NHEAD + h)) * SEQ + ns) * HD + fd) = ov;
            }
        }
    }
}

// ---------------------------------------------------------------------------
// Causal flash attention fp16 (FA2). CTA: 128 queries, 8 warps x 16 rows.
// Merged 64-key softmax with f16x2 exp: subtract rowmax in fp32, pack to
// half2, ex2.approx.f16x2 (1 MUFU / 2 elems), sum via hadd2 + f32; the ex2
// output IS the PV A-fragment (no separate pack).
// ---------------------------------------------------------------------------
static constexpr int LDH = 72;                       // halves; 144 B rows
static constexpr int OFFQ = 0;
static constexpr int KVT_H = 64 * LDH;               // 4608 halves per K or V tile
static constexpr int OFFKV = 128 * LDH;
static constexpr int ATT_SMEM = (OFFKV + 4 * KVT_H) * 2;  // 55296 B

__global__ __launch_bounds__(256, 2) void attn_fa_kernel(float* __restrict__ out)
{
    extern __shared__ __half sh[];
    const int tid = threadIdx.x, wid = tid >> 5, lane = tid & 31;
    const int t4 = lane & 3, g = lane >> 2;
    const int qt = (int)gridDim.x - 1 - (int)blockIdx.x;  // heavy tiles first
    const int bh = blockIdx.y;
    const int qbase = qt * 128;

    const __half* Qg = g_q + (size_t)bh * SEQ * HD + (size_t)qbase * HD;
    const __half* Kg = g_k + (size_t)bh * SEQ * HD;
    const __half* Vg = g_v + (size_t)bh * SEQ * HD;

    const uint32_t sb = smem_u32(sh);

    #pragma unroll
    for (int q = 0; q < 4; q++) {
        int c = tid + q * 256;
        int row = c >> 3, ch = (c & 7) * 8;
        cp16(sb + (OFFQ + row * LDH + ch) * 2, Qg + (size_t)row * HD + ch);
    }
    cp_commit();

    auto load_kv = [&](int st, int jt) {
        uint32_t kb = sb + (OFFKV + st * 2 * KVT_H) * 2;
        const __half* kg = Kg + (size_t)jt * 64 * HD;
        const __half* vg = Vg + (size_t)jt * 64 * HD;
        #pragma unroll
        for (int q = 0; q < 2; q++) {
            int c = tid + q * 256;
            int row = c >> 3, ch = (c & 7) * 8;
            cp16(kb + (row * LDH + ch) * 2, kg + (size_t)row * HD + ch);
            cp16(kb + (KVT_H + row * LDH + ch) * 2, vg + (size_t)row * HD + ch);
        }
    };

    load_kv(0, 0);
    cp_commit();
    cp_wait<1>();
    __syncthreads();

    const int lrow16 = lane & 15;
    const int lcol8 = (lane >> 4) * 8;
    uint32_t qf[4][4];
    #pragma unroll
    for (int kc = 0; kc < 4; kc++)
        ldmx4(qf[kc], sb + (OFFQ + (wid * 16 + lrow16) * LDH + kc * 16 + lcol8) * 2);

    float oacc[8][4];
    #pragma unroll
    for (int j = 0; j < 8; j++)
        #pragma unroll
        for (int r = 0; r < 4; r++) oacc[j][r] = 0.f;
    float mrow[2] = {-1e30f, -1e30f};
    float lrow[2] = {0.f, 0.f};

    const int wrmin = qbase + wid * 16;
    const int wrmax = wrmin + 15;
    const int ntiles = 2 * qt + 2;

    const int v_row = ((lane >> 4) << 3) + (lane & 7);
    const int v_col = ((lane >> 3) & 1) * 8;

    for (int jt = 0; jt < ntiles; jt++) {
        if (jt + 1 < ntiles) load_kv((jt + 1) & 1, jt + 1);
        cp_commit();
        cp_wait<1>();
        __syncthreads();

        const int kb0 = jt * 64;
        uint32_t Ks = sb + (OFFKV + (jt & 1) * 2 * KVT_H) * 2;
        uint32_t Vs = Ks + KVT_H * 2;

        if (kb0 <= wrmax) {
            // ---- S = Q @ K^T (64 keys) ----
            float sacc[8][4];
            #pragma unroll
            for (int j = 0; j < 8; j++)
                #pragma unroll
                for (int r = 0; r < 4; r++) sacc[j][r] = 0.f;

            #pragma unroll
            for (int kc = 0; kc < 4; kc++) {
                #pragma unroll
                for (int np = 0; np < 4; np++) {
                    uint32_t bf[4];
                    ldmx4(bf, Ks + ((np * 16 + lrow16) * LDH + kc * 16 + lcol8) * 2);
                    mma_f16(sacc[2 * np + 0], qf[kc], bf[0], bf[2]);
                    mma_f16(sacc[2 * np + 1], qf[kc], bf[1], bf[3]);
                }
            }

            // ---- causal mask (diagonal region only) ----
            if (kb0 + 63 > wrmin) {
                #pragma unroll
                for (int nf = 0; nf < 8; nf++) {
                    int key = kb0 + nf * 8 + 2 * t4;
                    #pragma unroll
                    for (int r = 0; r < 2; r++) {
                        int qrow = wrmin + r * 8 + g;
                        if (key > qrow)     sacc[nf][r * 2 + 0] = -1e30f;
                        if (key + 1 > qrow) sacc[nf][r * 2 + 1] = -1e30f;
                    }
                }
            }

            // ---- rowmax (fp32) + alpha ----
            float alpha[2], mn2[2];
            #pragma unroll
            for (int r = 0; r < 2; r++) {
                float mx = fmaxf(sacc[0][r * 2], sacc[0][r * 2 + 1]);
                #pragma unroll
                for (int nf = 1; nf < 8; nf++)
                    mx = fmaxf(mx, fmaxf(sacc[nf][r * 2], sacc[nf][r * 2 + 1]));
                mx = fmaxf(mx, __shfl_xor_sync(0xffffffffu, mx, 1));
                mx = fmaxf(mx, __shfl_xor_sync(0xffffffffu, mx, 2));
                float mn = fmaxf(mrow[r], mx);
                alpha[r] = ex2f(mrow[r] - mn);
                mrow[r] = mn;
                mn2[r] = mn;
            }

            // ---- exp in f16x2: sub fp32, pack, ex2.f16x2 (P born packed) ----
            __half2 ph2[8][2];
            #pragma unroll
            for (int nf = 0; nf < 8; nf++)
                #pragma unroll
                for (int r = 0; r < 2; r++)
                    ph2[nf][r] = h2ex2(__floats2half2_rn(sacc[nf][r * 2 + 0] - mn2[r],
                                                         sacc[nf][r * 2 + 1] - mn2[r]));

            // ---- row sum: hadd2 pairs (<=2 each) then f32 ----
            #pragma unroll
            for (int r = 0; r < 2; r++) {
                __half2 q01 = __hadd2(ph2[0][r], ph2[1][r]);
                __half2 q23 = __hadd2(ph2[2][r], ph2[3][r]);
                __half2 q45 = __hadd2(ph2[4][r], ph2[5][r]);
                __half2 q67 = __hadd2(ph2[6][r], ph2[7][r]);
                float2 f0 = __half22float2(q01);
                float2 f1 = __half22float2(q23);
                float2 f2 = __half22float2(q45);
                float2 f3 = __half22float2(q67);
                float rs = ((f0.x + f0.y) + (f1.x + f1.y)) + ((f2.x + f2.y) + (f3.x + f3.y));
                rs += __shfl_xor_sync(0xffffffffu, rs, 1);
                rs += __shfl_xor_sync(0xffffffffu, rs, 2);
                lrow[r] = lrow[r] * alpha[r] + rs;
            }

            // ---- O rescale ----
            #pragma unroll
            for (int nf = 0; nf < 8; nf++) {
                oacc[nf][0] *= alpha[0]; oacc[nf][1] *= alpha[0];
                oacc[nf][2] *= alpha[1]; oacc[nf][3] *= alpha[1];
            }

            // ---- O += P @ V ----
            #pragma unroll
            for (int kc2 = 0; kc2 < 4; kc2++) {
                uint32_t a[4] = {*(uint32_t*)&ph2[2 * kc2][0],     *(uint32_t*)&ph2[2 * kc2][1],
                                 *(uint32_t*)&ph2[2 * kc2 + 1][0], *(uint32_t*)&ph2[2 * kc2 + 1][1]};
                #pragma unroll
                for (int np = 0; np < 4; np++) {
                    uint32_t bf[4];
                    ldmx4t(bf, Vs + ((kc2 * 16 + v_row) * LDH + np * 16 + v_col) * 2);
                    mma_f16(oacc[2 * np + 0], a, bf[0], bf[2]);
                    mma_f16(oacc[2 * np + 1], a, bf[1], bf[3]);
                }
            }
        }
        __syncthreads();
    }

    // ---- epilogue ----
    const int b = bh >> 4, h = bh & (NHEAD - 1);
    #pragma unroll
    for (int r = 0; r < 2; r++) {
        int qrow = qbase + wid * 16 + r * 8 + g;
        float inv = 1.0f / lrow[r];
        float* op = out + ((size_t)(b * SEQ + qrow)) * EMB + h * HD;
        #pragma unroll
        for (int nf = 0; nf < 8; nf++) {
            float2 ov = make_float2(oacc[nf][r * 2] * inv, oacc[nf][r * 2 + 1] * inv);
            *(float2*)(op + nf * 8 + 2 * t4) = ov;
        }
    }
}

// ---------------------------------------------------------------------------
// Host launcher
// ---------------------------------------------------------------------------
extern "C" void kernel_launch(void* const* d_in, const int* in_sizes, int n_in,
                              void* d_out, int out_size)
{
    const float* x    = (const float*)d_in[0];  // [2,2048,1024]
    const float* W    = (const float*)d_in[1];  // [16,1024,192]
    const float* bias = (const float*)d_in[2];  // [16,192]
    float* out = (float*)d_out;                 // [2,2048,1024]

    round_x_kernel<<<(ROWS * EMB / 4) / 256, 256>>>((const float4*)x);
    wtrans_kernel<<<dim3(EMB / 32, FDIM / 32, NHEAD), dim3(32, 8)>>>(W);

    static bool smem_set = false;
    if (!smem_set) {
        cudaFuncSetAttribute(qkv_mma_kernel, cudaFuncAttributeMaxDynamicSharedMemorySize, QKV_SMEM);
        cudaFuncSetAttribute(attn_fa_kernel, cudaFuncAttributeMaxDynamicSharedMemorySize, ATT_SMEM);
        smem_set = true;
    }
    qkv_mma_kernel<<<dim3(ROWS / CTA_M, NTOT / CTA_N), 128, QKV_SMEM>>>(bias);

    attn_fa_kernel<<<dim3(SEQ / 128, BATCH * NHEAD), 256, ATT_SMEM>>>(out);
}